// round 7
// baseline (speedup 1.0000x reference)
#include <cuda_runtime.h>
#include <math.h>

#define BB 128
#define TT 512
#define HH 1024
#define SS 128
#define KK 64
#define HIDV 512
#define DD 1152
#define G3 3072
#define GRID 128
#define NTHR 256

// ---------------- scratch (device globals; no allocation allowed) ----------
__device__ float g_Mse[KK * G3];                    // E @ W_ih_e^T  [k][j]
__device__ float g_Gx[(size_t)TT * BB * G3];        // [t][b][3H]
__device__ float g_hbuf[2][BB * HH];                // double-buffered hidden
__device__ float g_state[BB * KK];                  // current soft state
__device__ float g_a1[BB * HIDV];                   // tanh(h@W1^T+b1)
__device__ unsigned g_cnt;
__device__ unsigned g_epoch;

// ---------------- init: h=0, state=initial_state, barrier reset ------------
__global__ void k_init(const float* __restrict__ init_state) {
    int idx = blockIdx.x * blockDim.x + threadIdx.x;
    if (idx < BB * HH) g_hbuf[0][idx] = 0.0f;
    if (idx < BB * KK) g_state[idx] = init_state[idx];
    if (idx == 0) { g_cnt = 0u; g_epoch = 0u; }
}

// ---------------- Mse[k][j] = sum_s E[k][s] * W_ih[j][H+s] -----------------
__global__ void k_mse(const float* __restrict__ E, const float* __restrict__ Wih) {
    int j = blockIdx.x;                 // 0..3071
    __shared__ float w[SS];
    for (int s = threadIdx.x; s < SS; s += 64)
        w[s] = Wih[(size_t)j * DD + HH + s];
    __syncthreads();
    int k = threadIdx.x;                // 0..63
    float acc = 0.0f;
#pragma unroll 8
    for (int s = 0; s < SS; s++) acc += E[k * SS + s] * w[s];
    g_Mse[k * G3 + j] = acc;
}

// ---------------- Gx = contexts @ W_ih[:, :H]^T + b_ih ---------------------
// classic 128x128x8 SGEMM, 256 threads, 8x8 microtile
__global__ void k_gx(const float* __restrict__ ctx, const float* __restrict__ W,
                     const float* __restrict__ bih) {
    __shared__ float As[8][128];
    __shared__ float Bs[8][128];
    int tid = threadIdx.x;
    int m0 = blockIdx.y * 128, j0 = blockIdx.x * 128;
    int row = tid >> 1, c = (tid & 1) * 4;
    int tx = tid & 15, ty = tid >> 4;
    float acc[8][8];
#pragma unroll
    for (int i = 0; i < 8; i++)
#pragma unroll
        for (int j = 0; j < 8; j++) acc[i][j] = 0.0f;

    const float* aptr = ctx + (size_t)(m0 + row) * HH + c;
    const float* bptr = W + (size_t)(j0 + row) * DD + c;

    for (int k0 = 0; k0 < HH; k0 += 8) {
        float4 av = *(const float4*)(aptr + k0);
        float4 bv = *(const float4*)(bptr + k0);
        __syncthreads();
        As[c + 0][row] = av.x; As[c + 1][row] = av.y;
        As[c + 2][row] = av.z; As[c + 3][row] = av.w;
        Bs[c + 0][row] = bv.x; Bs[c + 1][row] = bv.y;
        Bs[c + 2][row] = bv.z; Bs[c + 3][row] = bv.w;
        __syncthreads();
#pragma unroll
        for (int k = 0; k < 8; k++) {
            float a[8], b[8];
            *(float4*)&a[0] = *(const float4*)&As[k][ty * 8];
            *(float4*)&a[4] = *(const float4*)&As[k][ty * 8 + 4];
            *(float4*)&b[0] = *(const float4*)&Bs[k][tx * 8];
            *(float4*)&b[4] = *(const float4*)&Bs[k][tx * 8 + 4];
#pragma unroll
            for (int i = 0; i < 8; i++)
#pragma unroll
                for (int j = 0; j < 8; j++) acc[i][j] += a[i] * b[j];
        }
    }
#pragma unroll
    for (int i = 0; i < 8; i++) {
        int m = m0 + ty * 8 + i;
        int bb = m >> 9;          // m / T
        int t  = m & 511;         // m % T
        float* dst = g_Gx + ((size_t)t * BB + bb) * G3 + j0 + tx * 8;
#pragma unroll
        for (int j = 0; j < 8; j++)
            dst[j] = acc[i][j] + bih[j0 + tx * 8 + j];
    }
}

// ---------------- software grid barrier (all GRID blocks co-resident) ------
__device__ __forceinline__ void gsync(unsigned target) {
    __syncthreads();
    if (threadIdx.x == 0) {
        __threadfence();
        if (atomicAdd(&g_cnt, 1u) == GRID - 1u) {
            g_cnt = 0u;
            __threadfence();
            atomicExch(&g_epoch, target);
        } else {
            while (*(volatile unsigned*)&g_epoch < target) { __nanosleep(64); }
        }
        __threadfence();
    }
    __syncthreads();
}

// ---------------- persistent sequence kernel --------------------------------
// 128 blocks x 256 threads, 3 phases per timestep, 3 grid barriers per step.
__global__ void __launch_bounds__(NTHR, 2)
k_seq(const float* __restrict__ Whh, const float* __restrict__ bhh,
      const float* __restrict__ W1, const float* __restrict__ b1,
      const float* __restrict__ W2, const float* __restrict__ b2,
      float* __restrict__ out)
{
    __shared__ float sh[2048];          // 8 KB, overlaid per phase
    const int tid = threadIdx.x;
    const int blk = blockIdx.x;
    unsigned bar = 1;

    // Phase A tile: 32 batch x 32 hidden-cols, thread microtile 2x2 (x3 gates)
    const int a_b0 = (blk >> 5) * 32;
    const int a_i0 = (blk & 31) * 32;
    const int ty = tid >> 4;            // 0..15 (batch pairs)
    const int tx = tid & 15;            // 0..15 (col pairs)
    const int lr = tid >> 2;            // loader row (tid<128 -> 0..31)
    const int lc = (tid & 3) * 4;       // loader k offset

    for (int t = 0; t < TT; t++) {
        const float* hcur = g_hbuf[t & 1];
        float* hnxt = g_hbuf[(t & 1) ^ 1];

        // ================= Phase A: recurrent GEMM + gates =================
        float aR[2][2] = {}, aZ[2][2] = {}, aNH[2][2] = {}, aNI[2][2] = {};

        // hidden part: k in [0,1024) over (h, Whh)
        for (int k0 = 0; k0 < HH; k0 += 16) {
            if (tid < 128) {
                float4 v = *(const float4*)&hcur[(a_b0 + lr) * HH + k0 + lc];
                sh[(lc + 0) * 32 + lr] = v.x; sh[(lc + 1) * 32 + lr] = v.y;
                sh[(lc + 2) * 32 + lr] = v.z; sh[(lc + 3) * 32 + lr] = v.w;
            }
            for (int q = tid; q < 384; q += NTHR) {      // 96 rows x 4 float4s
                int row = q >> 2, c = (q & 3) * 4;
                int jr = a_i0 + (row < 32 ? row : row < 64 ? 1024 + row - 32
                                                           : 2048 + row - 64);
                float4 w = *(const float4*)&Whh[(size_t)jr * HH + k0 + c];
                sh[512 + (c + 0) * 96 + row] = w.x;
                sh[512 + (c + 1) * 96 + row] = w.y;
                sh[512 + (c + 2) * 96 + row] = w.z;
                sh[512 + (c + 3) * 96 + row] = w.w;
            }
            __syncthreads();
#pragma unroll
            for (int k = 0; k < 16; k++) {
                float2 a  = *(float2*)&sh[k * 32 + ty * 2];
                float2 br = *(float2*)&sh[512 + k * 96 + tx * 2];
                float2 bz = *(float2*)&sh[512 + k * 96 + 32 + tx * 2];
                float2 bn = *(float2*)&sh[512 + k * 96 + 64 + tx * 2];
                aR[0][0] += a.x * br.x; aR[0][1] += a.x * br.y;
                aR[1][0] += a.y * br.x; aR[1][1] += a.y * br.y;
                aZ[0][0] += a.x * bz.x; aZ[0][1] += a.x * bz.y;
                aZ[1][0] += a.y * bz.x; aZ[1][1] += a.y * bz.y;
                aNH[0][0] += a.x * bn.x; aNH[0][1] += a.x * bn.y;
                aNH[1][0] += a.y * bn.x; aNH[1][1] += a.y * bn.y;
            }
            __syncthreads();
        }

        // state part: k in [0,64) over (state, Mse)
        for (int k0 = 0; k0 < KK; k0 += 16) {
            if (tid < 128) {
                float4 v = *(const float4*)&g_state[(a_b0 + lr) * KK + k0 + lc];
                sh[(lc + 0) * 32 + lr] = v.x; sh[(lc + 1) * 32 + lr] = v.y;
                sh[(lc + 2) * 32 + lr] = v.z; sh[(lc + 3) * 32 + lr] = v.w;
            }
            for (int q = tid; q < 384; q += NTHR) {      // 16 k x 24 float4s
                int k = q / 24, cc = (q % 24) * 4;
                int jm = a_i0 + (cc < 32 ? cc : cc < 64 ? 1024 + cc - 32
                                                        : 2048 + cc - 64);
                float4 m = *(const float4*)&g_Mse[(size_t)(k0 + k) * G3 + jm];
                sh[512 + k * 96 + cc + 0] = m.x;
                sh[512 + k * 96 + cc + 1] = m.y;
                sh[512 + k * 96 + cc + 2] = m.z;
                sh[512 + k * 96 + cc + 3] = m.w;
            }
            __syncthreads();
#pragma unroll
            for (int k = 0; k < 16; k++) {
                float2 a  = *(float2*)&sh[k * 32 + ty * 2];
                float2 br = *(float2*)&sh[512 + k * 96 + tx * 2];
                float2 bz = *(float2*)&sh[512 + k * 96 + 32 + tx * 2];
                float2 bn = *(float2*)&sh[512 + k * 96 + 64 + tx * 2];
                aR[0][0] += a.x * br.x; aR[0][1] += a.x * br.y;
                aR[1][0] += a.y * br.x; aR[1][1] += a.y * br.y;
                aZ[0][0] += a.x * bz.x; aZ[0][1] += a.x * bz.y;
                aZ[1][0] += a.y * bz.x; aZ[1][1] += a.y * bz.y;
                aNI[0][0] += a.x * bn.x; aNI[0][1] += a.x * bn.y;
                aNI[1][0] += a.y * bn.x; aNI[1][1] += a.y * bn.y;
            }
            __syncthreads();
        }

        // gates epilogue -> h_new
        {
            const float* gx = g_Gx + (size_t)t * BB * G3;
#pragma unroll
            for (int i2 = 0; i2 < 2; i2++) {
                int b = a_b0 + ty * 2 + i2;
                const float* gxb = gx + (size_t)b * G3;
                const float* hb = &hcur[b * HH];
                float* hnb = &hnxt[b * HH];
#pragma unroll
                for (int j2 = 0; j2 < 2; j2++) {
                    int ii = a_i0 + tx * 2 + j2;
                    float Sr = aR[i2][j2] + gxb[ii] + bhh[ii];
                    float Sz = aZ[i2][j2] + gxb[1024 + ii] + bhh[1024 + ii];
                    float An = aNI[i2][j2] + gxb[2048 + ii];
                    float Hn = aNH[i2][j2] + bhh[2048 + ii];
                    float r = 1.0f / (1.0f + expf(-Sr));
                    float z = 1.0f / (1.0f + expf(-Sz));
                    float n = tanhf(An + r * Hn);
                    hnb[ii] = (1.0f - z) * n + z * hb[ii];
                }
            }
        }
        gsync(bar++);

        // ================= Phase B: a1 = tanh(h_new @ W1^T + b1) ===========
        {
            const int b_b0 = (blk >> 5) * 32;
            const int b_o0 = (blk & 31) * 16;
            const int bty = tid >> 3;   // 0..31 (batch)
            const int btx = tid & 7;    // 0..7  (output pairs)
            float c0 = 0.0f, c1 = 0.0f;
            for (int k0 = 0; k0 < HH; k0 += 16) {
                if (tid < 128) {
                    float4 v = *(const float4*)&hnxt[(b_b0 + lr) * HH + k0 + lc];
                    sh[(lc + 0) * 32 + lr] = v.x; sh[(lc + 1) * 32 + lr] = v.y;
                    sh[(lc + 2) * 32 + lr] = v.z; sh[(lc + 3) * 32 + lr] = v.w;
                }
                if (tid < 64) {
                    int row = tid >> 2, c = (tid & 3) * 4;
                    float4 w = *(const float4*)&W1[(size_t)(b_o0 + row) * HH + k0 + c];
                    sh[512 + (c + 0) * 16 + row] = w.x;
                    sh[512 + (c + 1) * 16 + row] = w.y;
                    sh[512 + (c + 2) * 16 + row] = w.z;
                    sh[512 + (c + 3) * 16 + row] = w.w;
                }
                __syncthreads();
#pragma unroll
                for (int k = 0; k < 16; k++) {
                    float a = sh[k * 32 + bty];
                    float2 w = *(float2*)&sh[512 + k * 16 + btx * 2];
                    c0 += a * w.x; c1 += a * w.y;
                }
                __syncthreads();
            }
            int b = b_b0 + bty, o = b_o0 + btx * 2;
            g_a1[b * HIDV + o]     = tanhf(c0 + b1[o]);
            g_a1[b * HIDV + o + 1] = tanhf(c1 + b1[o + 1]);
        }
        gsync(bar++);

        // ================= Phase C: logits + softmax state =================
        {
            int b = blk;                    // 128 blocks == 128 batches
            for (int i = tid; i < HIDV; i += NTHR) sh[i] = g_a1[b * HIDV + i];
            __syncthreads();
            int k = tid & 63, q = tid >> 6;
            const float* w = W2 + (size_t)k * HIDV + q * 128;
            const float* a = sh + q * 128;
            float p = 0.0f;
#pragma unroll 16
            for (int i = 0; i < 128; i++) p += a[i] * w[i];
            sh[512 + tid] = p;
            __syncthreads();
            if (tid < KK) {
                float lg = sh[512 + tid] + sh[512 + tid + 64] +
                           sh[512 + tid + 128] + sh[512 + tid + 192] + b2[tid];
                out[((size_t)b * TT + t) * KK + tid] = lg;   // raw logits
                sh[768 + tid] = fminf(fmaxf(lg, -10.0f), 10.0f);
            }
            __syncthreads();
            if (tid < 32) {
                float x0 = sh[768 + tid], x1 = sh[768 + tid + 32];
                float m = fmaxf(x0, x1);
#pragma unroll
                for (int o = 16; o; o >>= 1) m = fmaxf(m, __shfl_xor_sync(0xffffffffu, m, o));
                float e0 = expf(x0 - m), e1 = expf(x1 - m);
                float s = e0 + e1;
#pragma unroll
                for (int o = 16; o; o >>= 1) s += __shfl_xor_sync(0xffffffffu, s, o);
                float inv = 1.0f / s;
                g_state[b * KK + tid]      = e0 * inv;
                g_state[b * KK + tid + 32] = e1 * inv;
            }
        }
        gsync(bar++);
    }
}

// ---------------- host launch -----------------------------------------------
extern "C" void kernel_launch(void* const* d_in, const int* in_sizes, int n_in,
                              void* d_out, int out_size) {
    const float* ctx  = (const float*)d_in[0];   // [B,T,H]
    const float* init = (const float*)d_in[1];   // [B,K]
    const float* E    = (const float*)d_in[2];   // [K,S]
    const float* Wih  = (const float*)d_in[3];   // [3H,D]
    const float* Whh  = (const float*)d_in[4];   // [3H,H]
    const float* bih  = (const float*)d_in[5];   // [3H]
    const float* bhh  = (const float*)d_in[6];   // [3H]
    const float* W1   = (const float*)d_in[7];   // [HID,H]
    const float* b1   = (const float*)d_in[8];   // [HID]
    const float* W2   = (const float*)d_in[9];   // [K,HID]
    const float* b2   = (const float*)d_in[10];  // [K]
    float* out = (float*)d_out;                  // [B,T,K] fp32

    k_init<<<512, 256>>>(init);
    k_mse<<<G3, 64>>>(E, Wih);
    k_gx<<<dim3(G3 / 128, (BB * TT) / 128), 256>>>(ctx, Wih, bih);
    k_seq<<<GRID, NTHR>>>(Whh, bhh, W1, b1, W2, b2, out);
}

// round 8
// speedup vs baseline: 1.2956x; 1.2956x over previous
#include <cuda_runtime.h>
#include <math.h>

#define BB 128
#define TT 512
#define HH 1024
#define SS 128
#define KK 64
#define HIDV 512
#define DD 1152
#define G3 3072
#define GRID 128
#define NTHR 256

// ---------------- scratch (device globals; no allocation allowed) ----------
__device__ float g_Mse[KK * G3];                    // E @ W_ih_e^T  [k][j]
__device__ float g_Gx[(size_t)TT * BB * G3];        // [t][b][3H]
__device__ float g_hbuf[2][BB * HH];                // double-buffered hidden
__device__ float g_state[BB * KK];                  // current soft state
__device__ float g_a1[BB * HIDV];                   // tanh(h@W1^T+b1)
__device__ unsigned g_cnt;
__device__ unsigned g_epoch;

// ---------------- init: h=0, state=initial_state, barrier reset ------------
__global__ void k_init(const float* __restrict__ init_state) {
    int idx = blockIdx.x * blockDim.x + threadIdx.x;
    if (idx < BB * HH) g_hbuf[0][idx] = 0.0f;
    if (idx < BB * KK) g_state[idx] = init_state[idx];
    if (idx == 0) { g_cnt = 0u; g_epoch = 0u; }
}

// ---------------- Mse[k][j] = sum_s E[k][s] * W_ih[j][H+s] -----------------
__global__ void k_mse(const float* __restrict__ E, const float* __restrict__ Wih) {
    int j = blockIdx.x;
    __shared__ float w[SS];
    for (int s = threadIdx.x; s < SS; s += 64)
        w[s] = Wih[(size_t)j * DD + HH + s];
    __syncthreads();
    int k = threadIdx.x;
    float acc = 0.0f;
#pragma unroll 8
    for (int s = 0; s < SS; s++) acc += E[k * SS + s] * w[s];
    g_Mse[k * G3 + j] = acc;
}

// ---------------- Gx = contexts @ W_ih[:, :H]^T + b_ih ---------------------
// 128x128x8 SGEMM, double-buffered smem, 256 threads, 8x8 microtile
__global__ void __launch_bounds__(256, 2)
k_gx(const float* __restrict__ ctx, const float* __restrict__ W,
     const float* __restrict__ bih) {
    __shared__ float As[2][8][128];
    __shared__ float Bs[2][8][128];
    int tid = threadIdx.x;
    int m0 = blockIdx.y * 128, j0 = blockIdx.x * 128;
    int row = tid >> 1, c = (tid & 1) * 4;
    int tx = tid & 15, ty = tid >> 4;
    float acc[8][8];
#pragma unroll
    for (int i = 0; i < 8; i++)
#pragma unroll
        for (int j = 0; j < 8; j++) acc[i][j] = 0.0f;

    const float* aptr = ctx + (size_t)(m0 + row) * HH + c;
    const float* bptr = W + (size_t)(j0 + row) * DD + c;

    float4 av = *(const float4*)(aptr);
    float4 bv = *(const float4*)(bptr);
    As[0][c + 0][row] = av.x; As[0][c + 1][row] = av.y;
    As[0][c + 2][row] = av.z; As[0][c + 3][row] = av.w;
    Bs[0][c + 0][row] = bv.x; Bs[0][c + 1][row] = bv.y;
    Bs[0][c + 2][row] = bv.z; Bs[0][c + 3][row] = bv.w;
    __syncthreads();

    for (int kt = 0; kt < 128; kt++) {
        int cur = kt & 1;
        if (kt < 127) {
            av = *(const float4*)(aptr + (kt + 1) * 8);
            bv = *(const float4*)(bptr + (kt + 1) * 8);
        }
#pragma unroll
        for (int k = 0; k < 8; k++) {
            float a[8], b[8];
            *(float4*)&a[0] = *(const float4*)&As[cur][k][ty * 8];
            *(float4*)&a[4] = *(const float4*)&As[cur][k][ty * 8 + 4];
            *(float4*)&b[0] = *(const float4*)&Bs[cur][k][tx * 8];
            *(float4*)&b[4] = *(const float4*)&Bs[cur][k][tx * 8 + 4];
#pragma unroll
            for (int i = 0; i < 8; i++)
#pragma unroll
                for (int j = 0; j < 8; j++) acc[i][j] += a[i] * b[j];
        }
        if (kt < 127) {
            int nb = cur ^ 1;
            As[nb][c + 0][row] = av.x; As[nb][c + 1][row] = av.y;
            As[nb][c + 2][row] = av.z; As[nb][c + 3][row] = av.w;
            Bs[nb][c + 0][row] = bv.x; Bs[nb][c + 1][row] = bv.y;
            Bs[nb][c + 2][row] = bv.z; Bs[nb][c + 3][row] = bv.w;
        }
        __syncthreads();
    }
#pragma unroll
    for (int i = 0; i < 8; i++) {
        int m = m0 + ty * 8 + i;
        int bb = m >> 9;
        int t  = m & 511;
        float* dst = g_Gx + ((size_t)t * BB + bb) * G3 + j0 + tx * 8;
#pragma unroll
        for (int j = 0; j < 8; j++)
            dst[j] = acc[i][j] + bih[j0 + tx * 8 + j];
    }
}

// ---------------- software grid barrier -------------------------------------
__device__ __forceinline__ void gsync(unsigned target) {
    __syncthreads();
    if (threadIdx.x == 0) {
        __threadfence();
        if (atomicAdd(&g_cnt, 1u) == GRID - 1u) {
            g_cnt = 0u;
            __threadfence();
            atomicExch(&g_epoch, target);
        } else {
            while (*(volatile unsigned*)&g_epoch < target) { __nanosleep(64); }
        }
        __threadfence();
    }
    __syncthreads();
}

// ---------------- persistent sequence kernel --------------------------------
// 128 blocks x 256 threads. Phase A: 32b x 32i x 3g tile, double-buffered
// smem, global + register prefetch, microtile 4b x 1i x 3g per thread.
__global__ void __launch_bounds__(NTHR, 2)
k_seq(const float* __restrict__ Whh, const float* __restrict__ bhh,
      const float* __restrict__ W1, const float* __restrict__ b1,
      const float* __restrict__ W2, const float* __restrict__ b2,
      float* __restrict__ out)
{
    __shared__ float sh[4096];          // 16 KB, overlaid per phase
    const int tid = threadIdx.x;
    const int blk = blockIdx.x;
    unsigned bar = 1;

    // Phase A mapping
    const int a_b0 = (blk >> 5) * 32;
    const int a_i0 = (blk & 31) * 32;
    const int bg = tid >> 5;            // 0..7 batch group (warp-uniform)
    const int il = tid & 31;            // 0..31 column within tile
    // loaders
    const int h_row = tid >> 2;         // 0..31 (tid<128)
    const int h_kq  = (tid & 3) * 4;
    const int wr0 = tid >> 2;           // 0..63 (W rows, q0=tid<256)
    const int jr0 = a_i0 + (wr0 < 32 ? wr0 : 1024 + wr0 - 32);
    const int wr1 = 64 + (tid >> 2);    // 64..95 (q1=tid+256, tid<128)
    const int jr1 = a_i0 + 2048 + (tid >> 2);
    // Mse loaders (state part): q0=tid, q1=tid+256
    const int mk0 = tid / 24,            mc0 = (tid % 24) * 4;
    const int mk1 = (tid + 256) / 24,    mc1 = ((tid + 256) % 24) * 4;
    const int mj0 = a_i0 + (mc0 < 32 ? mc0 : mc0 < 64 ? 1024 + mc0 - 32 : 2048 + mc0 - 64);
    const int mj1 = a_i0 + (mc1 < 32 ? mc1 : mc1 < 64 ? 1024 + mc1 - 32 : 2048 + mc1 - 64);

    // Phase B mapping
    const int lr = tid >> 2, lc = (tid & 3) * 4;

#define HS(buf, k, b)  sh[(buf) * 512 + (k) * 32 + (b)]
#define WS(buf, k, cc) sh[1024 + (buf) * 1536 + (k) * 96 + (cc)]

    for (int t = 0; t < TT; t++) {
        const float* hcur = g_hbuf[t & 1];
        float* hnxt = g_hbuf[(t & 1) ^ 1];

        // ================= Phase A =================
        float aR[4] = {}, aZ[4] = {}, aNH[4] = {}, aNI[4] = {};
        float4 hA, w0A, w1A;

        // ---- hidden part: 64 k-tiles over (h, Whh) ----
        if (tid < 128) hA = *(const float4*)&hcur[(a_b0 + h_row) * HH + h_kq];
        w0A = *(const float4*)&Whh[(size_t)jr0 * HH + h_kq];
        if (tid < 128) w1A = *(const float4*)&Whh[(size_t)jr1 * HH + h_kq];
        if (tid < 128) {
            HS(0, h_kq + 0, h_row) = hA.x; HS(0, h_kq + 1, h_row) = hA.y;
            HS(0, h_kq + 2, h_row) = hA.z; HS(0, h_kq + 3, h_row) = hA.w;
        }
        WS(0, h_kq + 0, wr0) = w0A.x; WS(0, h_kq + 1, wr0) = w0A.y;
        WS(0, h_kq + 2, wr0) = w0A.z; WS(0, h_kq + 3, wr0) = w0A.w;
        if (tid < 128) {
            WS(0, h_kq + 0, wr1) = w1A.x; WS(0, h_kq + 1, wr1) = w1A.y;
            WS(0, h_kq + 2, wr1) = w1A.z; WS(0, h_kq + 3, wr1) = w1A.w;
        }
        __syncthreads();

        for (int kt = 0; kt < 64; kt++) {
            const int cur = kt & 1;
            const int k0n = (kt + 1) * 16;
            if (kt < 63) {
                if (tid < 128) hA = *(const float4*)&hcur[(a_b0 + h_row) * HH + k0n + h_kq];
                w0A = *(const float4*)&Whh[(size_t)jr0 * HH + k0n + h_kq];
                if (tid < 128) w1A = *(const float4*)&Whh[(size_t)jr1 * HH + k0n + h_kq];
            }
            // compute (register-pipelined)
            {
                float4 a = *(const float4*)&HS(cur, 0, bg * 4);
                float br = WS(cur, 0, il), bz = WS(cur, 0, 32 + il), bn = WS(cur, 0, 64 + il);
#pragma unroll
                for (int k = 0; k < 16; k++) {
                    float4 a2; float br2, bz2, bn2;
                    if (k < 15) {
                        a2 = *(const float4*)&HS(cur, k + 1, bg * 4);
                        br2 = WS(cur, k + 1, il);
                        bz2 = WS(cur, k + 1, 32 + il);
                        bn2 = WS(cur, k + 1, 64 + il);
                    }
                    aR[0] += a.x * br; aR[1] += a.y * br; aR[2] += a.z * br; aR[3] += a.w * br;
                    aZ[0] += a.x * bz; aZ[1] += a.y * bz; aZ[2] += a.z * bz; aZ[3] += a.w * bz;
                    aNH[0] += a.x * bn; aNH[1] += a.y * bn; aNH[2] += a.z * bn; aNH[3] += a.w * bn;
                    if (k < 15) { a = a2; br = br2; bz = bz2; bn = bn2; }
                }
            }
            if (kt < 63) {
                const int nb = cur ^ 1;
                if (tid < 128) {
                    HS(nb, h_kq + 0, h_row) = hA.x; HS(nb, h_kq + 1, h_row) = hA.y;
                    HS(nb, h_kq + 2, h_row) = hA.z; HS(nb, h_kq + 3, h_row) = hA.w;
                }
                WS(nb, h_kq + 0, wr0) = w0A.x; WS(nb, h_kq + 1, wr0) = w0A.y;
                WS(nb, h_kq + 2, wr0) = w0A.z; WS(nb, h_kq + 3, wr0) = w0A.w;
                if (tid < 128) {
                    WS(nb, h_kq + 0, wr1) = w1A.x; WS(nb, h_kq + 1, wr1) = w1A.y;
                    WS(nb, h_kq + 2, wr1) = w1A.z; WS(nb, h_kq + 3, wr1) = w1A.w;
                }
            }
            __syncthreads();
        }

        // ---- state part: 4 k-tiles over (state, Mse) ----
        if (tid < 128) hA = *(const float4*)&g_state[(a_b0 + h_row) * KK + h_kq];
        w0A = *(const float4*)&g_Mse[(size_t)mk0 * G3 + mj0];
        if (tid < 128) w1A = *(const float4*)&g_Mse[(size_t)mk1 * G3 + mj1];
        if (tid < 128) {
            HS(0, h_kq + 0, h_row) = hA.x; HS(0, h_kq + 1, h_row) = hA.y;
            HS(0, h_kq + 2, h_row) = hA.z; HS(0, h_kq + 3, h_row) = hA.w;
        }
        *(float4*)&WS(0, mk0, mc0) = w0A;
        if (tid < 128) *(float4*)&WS(0, mk1, mc1) = w1A;
        __syncthreads();

        for (int kt = 0; kt < 4; kt++) {
            const int cur = kt & 1;
            const int k0n = (kt + 1) * 16;
            if (kt < 3) {
                if (tid < 128) hA = *(const float4*)&g_state[(a_b0 + h_row) * KK + k0n + h_kq];
                w0A = *(const float4*)&g_Mse[(size_t)(k0n + mk0) * G3 + mj0];
                if (tid < 128) w1A = *(const float4*)&g_Mse[(size_t)(k0n + mk1) * G3 + mj1];
            }
            {
                float4 a = *(const float4*)&HS(cur, 0, bg * 4);
                float br = WS(cur, 0, il), bz = WS(cur, 0, 32 + il), bn = WS(cur, 0, 64 + il);
#pragma unroll
                for (int k = 0; k < 16; k++) {
                    float4 a2; float br2, bz2, bn2;
                    if (k < 15) {
                        a2 = *(const float4*)&HS(cur, k + 1, bg * 4);
                        br2 = WS(cur, k + 1, il);
                        bz2 = WS(cur, k + 1, 32 + il);
                        bn2 = WS(cur, k + 1, 64 + il);
                    }
                    aR[0] += a.x * br; aR[1] += a.y * br; aR[2] += a.z * br; aR[3] += a.w * br;
                    aZ[0] += a.x * bz; aZ[1] += a.y * bz; aZ[2] += a.z * bz; aZ[3] += a.w * bz;
                    aNI[0] += a.x * bn; aNI[1] += a.y * bn; aNI[2] += a.z * bn; aNI[3] += a.w * bn;
                    if (k < 15) { a = a2; br = br2; bz = bz2; bn = bn2; }
                }
            }
            if (kt < 3) {
                const int nb = cur ^ 1;
                if (tid < 128) {
                    HS(nb, h_kq + 0, h_row) = hA.x; HS(nb, h_kq + 1, h_row) = hA.y;
                    HS(nb, h_kq + 2, h_row) = hA.z; HS(nb, h_kq + 3, h_row) = hA.w;
                }
                *(float4*)&WS(nb, mk0, mc0) = w0A;
                if (tid < 128) *(float4*)&WS(nb, mk1, mc1) = w1A;
            }
            __syncthreads();
        }

        // ---- gates epilogue -> h_new ----
        {
            const float* gx = g_Gx + (size_t)t * BB * G3;
            const int ii = a_i0 + il;
            const float bhr = bhh[ii], bhz = bhh[1024 + ii], bhn = bhh[2048 + ii];
#pragma unroll
            for (int i2 = 0; i2 < 4; i2++) {
                int b = a_b0 + bg * 4 + i2;
                const float* gxb = gx + (size_t)b * G3;
                float Sr = aR[i2] + gxb[ii] + bhr;
                float Sz = aZ[i2] + gxb[1024 + ii] + bhz;
                float An = aNI[i2] + gxb[2048 + ii];
                float Hn = aNH[i2] + bhn;
                float r = 1.0f / (1.0f + expf(-Sr));
                float z = 1.0f / (1.0f + expf(-Sz));
                float n = tanhf(An + r * Hn);
                hnxt[b * HH + ii] = (1.0f - z) * n + z * hcur[b * HH + ii];
            }
        }
        gsync(bar++);

        // ================= Phase B: a1 = tanh(h_new @ W1^T + b1) ===========
        {
            const int b_b0 = (blk >> 5) * 32;
            const int b_o0 = (blk & 31) * 16;
            const int bty = tid >> 3;   // 0..31 (batch)
            const int btx = tid & 7;    // 0..7  (output pairs)
            float c0 = 0.0f, c1 = 0.0f;
            for (int k0 = 0; k0 < HH; k0 += 16) {
                if (tid < 128) {
                    float4 v = *(const float4*)&hnxt[(b_b0 + lr) * HH + k0 + lc];
                    sh[(lc + 0) * 32 + lr] = v.x; sh[(lc + 1) * 32 + lr] = v.y;
                    sh[(lc + 2) * 32 + lr] = v.z; sh[(lc + 3) * 32 + lr] = v.w;
                }
                if (tid < 64) {
                    int row = tid >> 2, c = (tid & 3) * 4;
                    float4 w = *(const float4*)&W1[(size_t)(b_o0 + row) * HH + k0 + c];
                    sh[512 + (c + 0) * 16 + row] = w.x;
                    sh[512 + (c + 1) * 16 + row] = w.y;
                    sh[512 + (c + 2) * 16 + row] = w.z;
                    sh[512 + (c + 3) * 16 + row] = w.w;
                }
                __syncthreads();
#pragma unroll
                for (int k = 0; k < 16; k++) {
                    float a = sh[k * 32 + bty];
                    float2 w = *(float2*)&sh[512 + k * 16 + btx * 2];
                    c0 += a * w.x; c1 += a * w.y;
                }
                __syncthreads();
            }
            int b = b_b0 + bty, o = b_o0 + btx * 2;
            g_a1[b * HIDV + o]     = tanhf(c0 + b1[o]);
            g_a1[b * HIDV + o + 1] = tanhf(c1 + b1[o + 1]);
        }
        gsync(bar++);

        // ================= Phase C: logits + softmax state =================
        {
            int b = blk;
            for (int i = tid; i < HIDV; i += NTHR) sh[i] = g_a1[b * HIDV + i];
            __syncthreads();
            int k = tid & 63, q = tid >> 6;
            const float* w = W2 + (size_t)k * HIDV + q * 128;
            const float* a = sh + q * 128;
            float p = 0.0f;
#pragma unroll 16
            for (int i = 0; i < 128; i++) p += a[i] * w[i];
            sh[512 + tid] = p;
            __syncthreads();
            if (tid < KK) {
                float lg = sh[512 + tid] + sh[512 + tid + 64] +
                           sh[512 + tid + 128] + sh[512 + tid + 192] + b2[tid];
                out[((size_t)b * TT + t) * KK + tid] = lg;
                sh[768 + tid] = fminf(fmaxf(lg, -10.0f), 10.0f);
            }
            __syncthreads();
            if (tid < 32) {
                float x0 = sh[768 + tid], x1 = sh[768 + tid + 32];
                float m = fmaxf(x0, x1);
#pragma unroll
                for (int o = 16; o; o >>= 1) m = fmaxf(m, __shfl_xor_sync(0xffffffffu, m, o));
                float e0 = expf(x0 - m), e1 = expf(x1 - m);
                float s = e0 + e1;
#pragma unroll
                for (int o = 16; o; o >>= 1) s += __shfl_xor_sync(0xffffffffu, s, o);
                float inv = 1.0f / s;
                g_state[b * KK + tid]      = e0 * inv;
                g_state[b * KK + tid + 32] = e1 * inv;
            }
        }
        gsync(bar++);
    }
#undef HS
#undef WS
}

// ---------------- host launch -----------------------------------------------
extern "C" void kernel_launch(void* const* d_in, const int* in_sizes, int n_in,
                              void* d_out, int out_size) {
    const float* ctx  = (const float*)d_in[0];   // [B,T,H]
    const float* init = (const float*)d_in[1];   // [B,K]
    const float* E    = (const float*)d_in[2];   // [K,S]
    const float* Wih  = (const float*)d_in[3];   // [3H,D]
    const float* Whh  = (const float*)d_in[4];   // [3H,H]
    const float* bih  = (const float*)d_in[5];   // [3H]
    const float* bhh  = (const float*)d_in[6];   // [3H]
    const float* W1   = (const float*)d_in[7];   // [HID,H]
    const float* b1   = (const float*)d_in[8];   // [HID]
    const float* W2   = (const float*)d_in[9];   // [K,HID]
    const float* b2   = (const float*)d_in[10];  // [K]
    float* out = (float*)d_out;                  // [B,T,K] fp32

    k_init<<<512, 256>>>(init);
    k_mse<<<G3, 64>>>(E, Wih);
    k_gx<<<dim3(G3 / 128, (BB * TT) / 128), 256>>>(ctx, Wih, bih);
    k_seq<<<GRID, NTHR>>>(Whh, bhh, W1, b1, W2, b2, out);
}

// round 9
// speedup vs baseline: 1.4889x; 1.1492x over previous
#include <cuda_runtime.h>
#include <math.h>

#define BB 128
#define TT 512
#define HH 1024
#define SS 128
#define KK 64
#define HIDV 512
#define DD 1152
#define G3 3072
#define GRID 128
#define NTHR 512

// ---------------- scratch (device globals; no allocation allowed) ----------
__device__ float g_Mse[KK * G3];                    // E @ W_ih_e^T  [k][j]
__device__ float g_Gx[(size_t)TT * BB * G3];        // [t][b][3H]
__device__ float g_hbuf[2][BB * HH];                // double-buffered hidden
__device__ float g_state[BB * KK];                  // current soft state
__device__ float g_a1[BB * HIDV];                   // tanh(h@W1^T+b1)
__device__ unsigned g_cnt;
__device__ unsigned g_epoch;

// ---------------- init: h=0, state=initial_state, barrier reset ------------
__global__ void k_init(const float* __restrict__ init_state) {
    int idx = blockIdx.x * blockDim.x + threadIdx.x;
    if (idx < BB * HH) g_hbuf[0][idx] = 0.0f;
    if (idx < BB * KK) g_state[idx] = init_state[idx];
    if (idx == 0) { g_cnt = 0u; g_epoch = 0u; }
}

// ---------------- Mse[k][j] = sum_s E[k][s] * W_ih[j][H+s] -----------------
__global__ void k_mse(const float* __restrict__ E, const float* __restrict__ Wih) {
    int j = blockIdx.x;
    __shared__ float w[SS];
    for (int s = threadIdx.x; s < SS; s += 64)
        w[s] = Wih[(size_t)j * DD + HH + s];
    __syncthreads();
    int k = threadIdx.x;
    float acc = 0.0f;
#pragma unroll 8
    for (int s = 0; s < SS; s++) acc += E[k * SS + s] * w[s];
    g_Mse[k * G3 + j] = acc;
}

// ---------------- Gx = contexts @ W_ih[:, :H]^T + b_ih ---------------------
// 128x128x8 SGEMM, double-buffered smem, 256 threads, 8x8 microtile
__global__ void __launch_bounds__(256, 2)
k_gx(const float* __restrict__ ctx, const float* __restrict__ W,
     const float* __restrict__ bih) {
    __shared__ float As[2][8][128];
    __shared__ float Bs[2][8][128];
    int tid = threadIdx.x;
    int m0 = blockIdx.y * 128, j0 = blockIdx.x * 128;
    int row = tid >> 1, c = (tid & 1) * 4;
    int tx = tid & 15, ty = tid >> 4;
    float acc[8][8];
#pragma unroll
    for (int i = 0; i < 8; i++)
#pragma unroll
        for (int j = 0; j < 8; j++) acc[i][j] = 0.0f;

    const float* aptr = ctx + (size_t)(m0 + row) * HH + c;
    const float* bptr = W + (size_t)(j0 + row) * DD + c;

    float4 av = *(const float4*)(aptr);
    float4 bv = *(const float4*)(bptr);
    As[0][c + 0][row] = av.x; As[0][c + 1][row] = av.y;
    As[0][c + 2][row] = av.z; As[0][c + 3][row] = av.w;
    Bs[0][c + 0][row] = bv.x; Bs[0][c + 1][row] = bv.y;
    Bs[0][c + 2][row] = bv.z; Bs[0][c + 3][row] = bv.w;
    __syncthreads();

    for (int kt = 0; kt < 128; kt++) {
        int cur = kt & 1;
        if (kt < 127) {
            av = *(const float4*)(aptr + (kt + 1) * 8);
            bv = *(const float4*)(bptr + (kt + 1) * 8);
        }
#pragma unroll
        for (int k = 0; k < 8; k++) {
            float a[8], b[8];
            *(float4*)&a[0] = *(const float4*)&As[cur][k][ty * 8];
            *(float4*)&a[4] = *(const float4*)&As[cur][k][ty * 8 + 4];
            *(float4*)&b[0] = *(const float4*)&Bs[cur][k][tx * 8];
            *(float4*)&b[4] = *(const float4*)&Bs[cur][k][tx * 8 + 4];
#pragma unroll
            for (int i = 0; i < 8; i++)
#pragma unroll
                for (int j = 0; j < 8; j++) acc[i][j] += a[i] * b[j];
        }
        if (kt < 127) {
            int nb = cur ^ 1;
            As[nb][c + 0][row] = av.x; As[nb][c + 1][row] = av.y;
            As[nb][c + 2][row] = av.z; As[nb][c + 3][row] = av.w;
            Bs[nb][c + 0][row] = bv.x; Bs[nb][c + 1][row] = bv.y;
            Bs[nb][c + 2][row] = bv.z; Bs[nb][c + 3][row] = bv.w;
        }
        __syncthreads();
    }
#pragma unroll
    for (int i = 0; i < 8; i++) {
        int m = m0 + ty * 8 + i;
        int bb = m >> 9;
        int t  = m & 511;
        float* dst = g_Gx + ((size_t)t * BB + bb) * G3 + j0 + tx * 8;
#pragma unroll
        for (int j = 0; j < 8; j++)
            dst[j] = acc[i][j] + bih[j0 + tx * 8 + j];
    }
}

// ---------------- software grid barrier -------------------------------------
__device__ __forceinline__ void gsync(unsigned target) {
    __syncthreads();
    if (threadIdx.x == 0) {
        __threadfence();
        if (atomicAdd(&g_cnt, 1u) == GRID - 1u) {
            g_cnt = 0u;
            __threadfence();
            atomicExch(&g_epoch, target);
        } else {
            while (*(volatile unsigned*)&g_epoch < target) { __nanosleep(64); }
        }
        __threadfence();
    }
    __syncthreads();
}

// ---------------- persistent sequence kernel --------------------------------
// 128 blocks x 512 threads. Two 256-thread groups split the k dimension
// (alternating 16-wide k tiles), each with private double-buffered smem;
// partials reduced through smem before the gate epilogue.
__global__ void __launch_bounds__(NTHR, 1)
k_seq(const float* __restrict__ Whh, const float* __restrict__ bhh,
      const float* __restrict__ W1, const float* __restrict__ b1,
      const float* __restrict__ W2, const float* __restrict__ b2,
      float* __restrict__ out)
{
    __shared__ float sh[11264];         // 44 KB
    const int tid = threadIdx.x;
    const int blk = blockIdx.x;
    unsigned bar = 1;

    const int g  = tid >> 8;            // k-split group 0/1
    const int t2 = tid & 255;

    // Phase A mapping (per group)
    const int a_b0 = (blk >> 5) * 32;
    const int a_i0 = (blk & 31) * 32;
    const int bg = t2 >> 5;             // 0..7 batch group (warp-uniform)
    const int il = t2 & 31;             // column within tile
    const int h_row = t2 >> 2;          // (t2<128) -> 0..31
    const int h_kq  = (t2 & 3) * 4;
    const int wr0 = t2 >> 2;            // 0..63
    const int jr0 = a_i0 + (wr0 < 32 ? wr0 : 1024 + wr0 - 32);
    const int wr1 = 64 + (t2 >> 2);     // (t2<128)
    const int jr1 = a_i0 + 2048 + (t2 >> 2);
    const int mk0 = t2 / 24,          mc0 = (t2 % 24) * 4;
    const int mk1 = (t2 + 256) / 24,  mc1 = ((t2 + 256) % 24) * 4;
    const int mj0 = a_i0 + (mc0 < 32 ? mc0 : mc0 < 64 ? 1024 + mc0 - 32 : 2048 + mc0 - 64);
    const int mj1 = a_i0 + (mc1 < 32 ? mc1 : mc1 < 64 ? 1024 + mc1 - 32 : 2048 + mc1 - 64);

#define HS(gg, bf, k, b)  sh[(gg) * 1024 + (bf) * 512 + (k) * 32 + (b)]
#define WS(gg, bf, k, c)  sh[2048 + (gg) * 3072 + (bf) * 1536 + (k) * 96 + (c)]
#define GXS(b2, j2)       sh[8192 + (b2) * 96 + (j2)]

#define STORE_H(bf)                                                          \
    if (t2 < 128) {                                                          \
        HS(g, bf, h_kq + 0, h_row) = hA.x; HS(g, bf, h_kq + 1, h_row) = hA.y;\
        HS(g, bf, h_kq + 2, h_row) = hA.z; HS(g, bf, h_kq + 3, h_row) = hA.w;\
    }
#define STORE_W(bf)                                                          \
    WS(g, bf, h_kq + 0, wr0) = w0A.x; WS(g, bf, h_kq + 1, wr0) = w0A.y;      \
    WS(g, bf, h_kq + 2, wr0) = w0A.z; WS(g, bf, h_kq + 3, wr0) = w0A.w;      \
    if (t2 < 128) {                                                          \
        WS(g, bf, h_kq + 0, wr1) = w1A.x; WS(g, bf, h_kq + 1, wr1) = w1A.y;  \
        WS(g, bf, h_kq + 2, wr1) = w1A.z; WS(g, bf, h_kq + 3, wr1) = w1A.w;  \
    }
#define STORE_M(bf)                                                          \
    *(float4*)&WS(g, bf, mk0, mc0) = w0A;                                    \
    if (t2 < 128) *(float4*)&WS(g, bf, mk1, mc1) = w1A;

#define INNER16(bf, ACC)                                                     \
    {                                                                        \
        float4 a = *(const float4*)&HS(g, bf, 0, bg * 4);                    \
        float br = WS(g, bf, 0, il), bz = WS(g, bf, 0, 32 + il),             \
              bn = WS(g, bf, 0, 64 + il);                                    \
        _Pragma("unroll")                                                    \
        for (int k = 0; k < 16; k++) {                                       \
            float4 a2; float br2, bz2, bn2;                                  \
            if (k < 15) {                                                    \
                a2 = *(const float4*)&HS(g, bf, k + 1, bg * 4);              \
                br2 = WS(g, bf, k + 1, il);                                  \
                bz2 = WS(g, bf, k + 1, 32 + il);                             \
                bn2 = WS(g, bf, k + 1, 64 + il);                             \
            }                                                                \
            aR[0] += a.x * br; aR[1] += a.y * br;                            \
            aR[2] += a.z * br; aR[3] += a.w * br;                            \
            aZ[0] += a.x * bz; aZ[1] += a.y * bz;                            \
            aZ[2] += a.z * bz; aZ[3] += a.w * bz;                            \
            ACC[0] += a.x * bn; ACC[1] += a.y * bn;                          \
            ACC[2] += a.z * bn; ACC[3] += a.w * bn;                          \
            if (k < 15) { a = a2; br = br2; bz = bz2; bn = bn2; }            \
        }                                                                    \
    }

    for (int t = 0; t < TT; t++) {
        const float* hcur = g_hbuf[t & 1];
        float* hnxt = g_hbuf[(t & 1) ^ 1];

        // ---- stage this step's Gx tile to smem (hidden behind GEMM) ----
        {
            const float* gxt = g_Gx + (size_t)t * BB * G3;
            for (int q = tid; q < 3072; q += NTHR) {
                int b2 = q / 96, j2 = q % 96;
                int jg = a_i0 + (j2 < 32 ? j2 : j2 < 64 ? 1024 + j2 - 32
                                                        : 2048 + j2 - 64);
                GXS(b2, j2) = __ldg(gxt + (size_t)(a_b0 + b2) * G3 + jg);
            }
        }

        // ================= Phase A =================
        float aR[4] = {}, aZ[4] = {}, aNH[4] = {}, aNI[4] = {};
        float4 hA, w0A, w1A;

        // ---- hidden part: group g does k-tiles (2*kt+g)*16, kt=0..31 ----
        {
            int k0 = g * 16;
            if (t2 < 128) hA = *(const float4*)&hcur[(a_b0 + h_row) * HH + k0 + h_kq];
            w0A = *(const float4*)&Whh[(size_t)jr0 * HH + k0 + h_kq];
            if (t2 < 128) w1A = *(const float4*)&Whh[(size_t)jr1 * HH + k0 + h_kq];
            STORE_H(0) STORE_W(0)
        }
        __syncthreads();
        for (int kt = 0; kt < 32; kt++) {
            const int cur = kt & 1;
            if (kt < 31) {
                int k0n = ((kt + 1) * 2 + g) * 16;
                if (t2 < 128) hA = *(const float4*)&hcur[(a_b0 + h_row) * HH + k0n + h_kq];
                w0A = *(const float4*)&Whh[(size_t)jr0 * HH + k0n + h_kq];
                if (t2 < 128) w1A = *(const float4*)&Whh[(size_t)jr1 * HH + k0n + h_kq];
            }
            INNER16(cur, aNH)
            if (kt < 31) {
                const int nb = cur ^ 1;
                STORE_H(nb) STORE_W(nb)
            }
            __syncthreads();
        }

        // ---- state part: group g does k-tiles (2*kt+g)*16, kt=0..1 ----
        {
            int k0 = g * 16;
            if (t2 < 128) hA = *(const float4*)&g_state[(a_b0 + h_row) * KK + k0 + h_kq];
            w0A = *(const float4*)&g_Mse[(size_t)(k0 + mk0) * G3 + mj0];
            if (t2 < 128) w1A = *(const float4*)&g_Mse[(size_t)(k0 + mk1) * G3 + mj1];
            STORE_H(0) STORE_M(0)
        }
        __syncthreads();
        for (int kt = 0; kt < 2; kt++) {
            const int cur = kt & 1;
            if (kt < 1) {
                int k0n = (2 + g) * 16;
                if (t2 < 128) hA = *(const float4*)&g_state[(a_b0 + h_row) * KK + k0n + h_kq];
                w0A = *(const float4*)&g_Mse[(size_t)(k0n + mk0) * G3 + mj0];
                if (t2 < 128) w1A = *(const float4*)&g_Mse[(size_t)(k0n + mk1) * G3 + mj1];
            }
            INNER16(cur, aNI)
            if (kt < 1) {
                STORE_H(1) STORE_M(1)
            }
            __syncthreads();
        }

        // ---- cross-group reduction + gate epilogue (group 0 finishes) ----
        if (g == 1) {
            float* d = &sh[t2 * 16];
            *(float4*)&d[0]  = make_float4(aR[0],  aR[1],  aR[2],  aR[3]);
            *(float4*)&d[4]  = make_float4(aZ[0],  aZ[1],  aZ[2],  aZ[3]);
            *(float4*)&d[8]  = make_float4(aNH[0], aNH[1], aNH[2], aNH[3]);
            *(float4*)&d[12] = make_float4(aNI[0], aNI[1], aNI[2], aNI[3]);
        }
        __syncthreads();
        if (g == 0) {
            const float* s = &sh[t2 * 16];
            float pR[4], pZ[4], pNH[4], pNI[4];
            *(float4*)pR  = *(const float4*)&s[0];
            *(float4*)pZ  = *(const float4*)&s[4];
            *(float4*)pNH = *(const float4*)&s[8];
            *(float4*)pNI = *(const float4*)&s[12];
            const int ii = a_i0 + il;
            const float bhr = bhh[ii], bhz = bhh[1024 + ii], bhn = bhh[2048 + ii];
#pragma unroll
            for (int i2 = 0; i2 < 4; i2++) {
                int b = a_b0 + bg * 4 + i2;
                float Sr = aR[i2] + pR[i2] + GXS(bg * 4 + i2, il) + bhr;
                float Sz = aZ[i2] + pZ[i2] + GXS(bg * 4 + i2, 32 + il) + bhz;
                float An = aNI[i2] + pNI[i2] + GXS(bg * 4 + i2, 64 + il);
                float Hn = aNH[i2] + pNH[i2] + bhn;
                float r = 1.0f / (1.0f + expf(-Sr));
                float z = 1.0f / (1.0f + expf(-Sz));
                float n = tanhf(An + r * Hn);
                hnxt[b * HH + ii] = (1.0f - z) * n + z * hcur[b * HH + ii];
            }
        }
        gsync(bar++);

        // ========== Phase B: a1 = tanh(h_new @ W1^T + b1), split-k x2 ======
        {
            const int b_o0 = (blk & 31) * 16;
            const int bty = t2 >> 3;    // 0..31 batch
            const int btx = t2 & 7;     // output pairs
            const int lr = t2 >> 2, lc = (t2 & 3) * 4;
            float c0 = 0.0f, c1 = 0.0f;
            for (int kt = 0; kt < 32; kt++) {
                int k0 = g * 512 + kt * 16;
                if (t2 < 128) {
                    float4 v = *(const float4*)&hnxt[(a_b0 + lr) * HH + k0 + lc];
                    sh[g * 512 + (lc + 0) * 32 + lr] = v.x;
                    sh[g * 512 + (lc + 1) * 32 + lr] = v.y;
                    sh[g * 512 + (lc + 2) * 32 + lr] = v.z;
                    sh[g * 512 + (lc + 3) * 32 + lr] = v.w;
                }
                if (t2 < 64) {
                    int row = t2 >> 2, c = (t2 & 3) * 4;
                    float4 w = *(const float4*)&W1[(size_t)(b_o0 + row) * HH + k0 + c];
                    sh[1024 + g * 256 + (c + 0) * 16 + row] = w.x;
                    sh[1024 + g * 256 + (c + 1) * 16 + row] = w.y;
                    sh[1024 + g * 256 + (c + 2) * 16 + row] = w.z;
                    sh[1024 + g * 256 + (c + 3) * 16 + row] = w.w;
                }
                __syncthreads();
#pragma unroll
                for (int k = 0; k < 16; k++) {
                    float a = sh[g * 512 + k * 32 + bty];
                    float2 w = *(const float2*)&sh[1024 + g * 256 + k * 16 + btx * 2];
                    c0 += a * w.x; c1 += a * w.y;
                }
                __syncthreads();
            }
            if (g == 1) {
                sh[2048 + t2 * 2] = c0; sh[2048 + t2 * 2 + 1] = c1;
            }
            __syncthreads();
            if (g == 0) {
                c0 += sh[2048 + t2 * 2]; c1 += sh[2048 + t2 * 2 + 1];
                int b = a_b0 + bty, o = b_o0 + btx * 2;
                g_a1[b * HIDV + o]     = tanhf(c0 + b1[o]);
                g_a1[b * HIDV + o + 1] = tanhf(c1 + b1[o + 1]);
            }
        }
        gsync(bar++);

        // ========== Phase C: logits + softmax state, split-k x8 ============
        {
            int b = blk;
            sh[tid] = g_a1[b * HIDV + tid];
            __syncthreads();
            int k = tid & 63, q = tid >> 6;
            const float* w = W2 + (size_t)k * HIDV + q * 64;
            const float* a = sh + q * 64;
            float p = 0.0f;
#pragma unroll 16
            for (int i = 0; i < 64; i++) p += a[i] * w[i];
            sh[512 + tid] = p;
            __syncthreads();
            if (tid < KK) {
                float lg = b2[tid];
#pragma unroll
                for (int q2 = 0; q2 < 8; q2++) lg += sh[512 + q2 * 64 + tid];
                out[((size_t)b * TT + t) * KK + tid] = lg;
                sh[1024 + tid] = fminf(fmaxf(lg, -10.0f), 10.0f);
            }
            __syncthreads();
            if (tid < 32) {
                float x0 = sh[1024 + tid], x1 = sh[1024 + tid + 32];
                float m = fmaxf(x0, x1);
#pragma unroll
                for (int o = 16; o; o >>= 1) m = fmaxf(m, __shfl_xor_sync(0xffffffffu, m, o));
                float e0 = expf(x0 - m), e1 = expf(x1 - m);
                float s = e0 + e1;
#pragma unroll
                for (int o = 16; o; o >>= 1) s += __shfl_xor_sync(0xffffffffu, s, o);
                float inv = 1.0f / s;
                g_state[b * KK + tid]      = e0 * inv;
                g_state[b * KK + tid + 32] = e1 * inv;
            }
        }
        gsync(bar++);
    }
#undef HS
#undef WS
#undef GXS
#undef STORE_H
#undef STORE_W
#undef STORE_M
#undef INNER16
}

// ---------------- host launch -----------------------------------------------
extern "C" void kernel_launch(void* const* d_in, const int* in_sizes, int n_in,
                              void* d_out, int out_size) {
    const float* ctx  = (const float*)d_in[0];   // [B,T,H]
    const float* init = (const float*)d_in[1];   // [B,K]
    const float* E    = (const float*)d_in[2];   // [K,S]
    const float* Wih  = (const float*)d_in[3];   // [3H,D]
    const float* Whh  = (const float*)d_in[4];   // [3H,H]
    const float* bih  = (const float*)d_in[5];   // [3H]
    const float* bhh  = (const float*)d_in[6];   // [3H]
    const float* W1   = (const float*)d_in[7];   // [HID,H]
    const float* b1   = (const float*)d_in[8];   // [HID]
    const float* W2   = (const float*)d_in[9];   // [K,HID]
    const float* b2   = (const float*)d_in[10];  // [K]
    float* out = (float*)d_out;                  // [B,T,K] fp32

    k_init<<<512, 256>>>(init);
    k_mse<<<G3, 64>>>(E, Wih);
    k_gx<<<dim3(G3 / 128, (BB * TT) / 128), 256>>>(ctx, Wih, bih);
    k_seq<<<GRID, NTHR>>>(Whh, bhh, W1, b1, W2, b2, out);
}

// round 11
// speedup vs baseline: 1.9421x; 1.3044x over previous
#include <cuda_runtime.h>
#include <cuda_bf16.h>
#include <math.h>
#include <stdint.h>

#define BB 128
#define TT 512
#define HH 1024
#define SS 128
#define KK 64
#define HIDV 512
#define DD 1152
#define G3 3072
#define GRID 128
#define NTHR 512
#define KTOT 1088
#define NCH 17
// smem byte offsets within one buffer (stride 72 bf16 = 144 B rows)
#define A_HI 0
#define A_LO 4608
#define B_HI 9216
#define B_LO 23040
#define BUF_BYTES 36864
#define SMEM_DYN (2 * BUF_BYTES)

// ---------------- scratch (device globals; no allocation allowed) ----------
__device__ float g_Gx[(size_t)TT * BB * G3];                 // [t][b][3H]
__device__ float g_hbuf[2][BB * HH];
__device__ float g_state[BB * KK];
__device__ float g_a1[BB * HIDV];
__device__ __align__(16) __nv_bfloat16 g_Bhi[(size_t)G3 * KTOT];
__device__ __align__(16) __nv_bfloat16 g_Blo[(size_t)G3 * KTOT];
__device__ unsigned g_cnt;
__device__ unsigned g_epoch;

// ---------------- mma/ldmatrix helpers (sm_80-era PTX, compiles compute_103)
__device__ __forceinline__ void ldm4(uint32_t& r0, uint32_t& r1, uint32_t& r2,
                                     uint32_t& r3, uint32_t a) {
    asm volatile("ldmatrix.sync.aligned.m8n8.x4.shared.b16 {%0,%1,%2,%3}, [%4];"
                 : "=r"(r0), "=r"(r1), "=r"(r2), "=r"(r3) : "r"(a));
}
__device__ __forceinline__ void ldm2(uint32_t& r0, uint32_t& r1, uint32_t a) {
    asm volatile("ldmatrix.sync.aligned.m8n8.x2.shared.b16 {%0,%1}, [%2];"
                 : "=r"(r0), "=r"(r1) : "r"(a));
}
__device__ __forceinline__ void mma_bf16(float* c, uint32_t a0, uint32_t a1,
                                         uint32_t a2, uint32_t a3,
                                         uint32_t b0, uint32_t b1) {
    asm volatile("mma.sync.aligned.m16n8k16.row.col.f32.bf16.bf16.f32 "
                 "{%0,%1,%2,%3}, {%4,%5,%6,%7}, {%8,%9}, {%0,%1,%2,%3};"
                 : "+f"(c[0]), "+f"(c[1]), "+f"(c[2]), "+f"(c[3])
                 : "r"(a0), "r"(a1), "r"(a2), "r"(a3), "r"(b0), "r"(b1));
}
static __device__ __forceinline__ void split2(float a, float b,
                                              uint32_t& whi, uint32_t& wlo) {
    __nv_bfloat16 ha = __float2bfloat16(a), hb = __float2bfloat16(b);
    __nv_bfloat16 la = __float2bfloat16(a - __bfloat162float(ha));
    __nv_bfloat16 lb = __float2bfloat16(b - __bfloat162float(hb));
    whi = (uint32_t)__bfloat16_as_ushort(ha) | ((uint32_t)__bfloat16_as_ushort(hb) << 16);
    wlo = (uint32_t)__bfloat16_as_ushort(la) | ((uint32_t)__bfloat16_as_ushort(lb) << 16);
}

// ---------------- init ------------------------------------------------------
__global__ void k_init(const float* __restrict__ init_state) {
    int idx = blockIdx.x * blockDim.x + threadIdx.x;
    if (idx < BB * HH) g_hbuf[0][idx] = 0.0f;
    if (idx < BB * KK) g_state[idx] = init_state[idx];
    if (idx == 0) { g_cnt = 0u; g_epoch = 0u; }
}

// ---------------- k_prep: build B = [Whh | Mse^T] as bf16 hi/lo -------------
__global__ void k_prep(const float* __restrict__ Whh, const float* __restrict__ E,
                       const float* __restrict__ Wih) {
    int j = blockIdx.x;
    __shared__ float ws[SS];
    ws[threadIdx.x] = Wih[(size_t)j * DD + HH + threadIdx.x];
    __syncthreads();
    for (int col = threadIdx.x; col < KTOT; col += 128) {
        float v;
        if (col < HH) v = Whh[(size_t)j * HH + col];
        else {
            int kk = col - HH;
            float a = 0.0f;
#pragma unroll 8
            for (int s = 0; s < SS; s++) a += E[kk * SS + s] * ws[s];
            v = a;
        }
        __nv_bfloat16 hi = __float2bfloat16(v);
        __nv_bfloat16 lo = __float2bfloat16(v - __bfloat162float(hi));
        g_Bhi[(size_t)j * KTOT + col] = hi;
        g_Blo[(size_t)j * KTOT + col] = lo;
    }
}

// ---------------- Gx = contexts @ W_ih[:, :H]^T + b_ih (fp32 SGEMM) ---------
__global__ void __launch_bounds__(256, 2)
k_gx(const float* __restrict__ ctx, const float* __restrict__ W,
     const float* __restrict__ bih) {
    __shared__ float As[2][8][128];
    __shared__ float Bs[2][8][128];
    int tid = threadIdx.x;
    int m0 = blockIdx.y * 128, j0 = blockIdx.x * 128;
    int row = tid >> 1, c = (tid & 1) * 4;
    int tx = tid & 15, ty = tid >> 4;
    float acc[8][8];
#pragma unroll
    for (int i = 0; i < 8; i++)
#pragma unroll
        for (int j = 0; j < 8; j++) acc[i][j] = 0.0f;

    const float* aptr = ctx + (size_t)(m0 + row) * HH + c;
    const float* bptr = W + (size_t)(j0 + row) * DD + c;

    float4 av = *(const float4*)(aptr);
    float4 bv = *(const float4*)(bptr);
    As[0][c + 0][row] = av.x; As[0][c + 1][row] = av.y;
    As[0][c + 2][row] = av.z; As[0][c + 3][row] = av.w;
    Bs[0][c + 0][row] = bv.x; Bs[0][c + 1][row] = bv.y;
    Bs[0][c + 2][row] = bv.z; Bs[0][c + 3][row] = bv.w;
    __syncthreads();

    for (int kt = 0; kt < 128; kt++) {
        int cur = kt & 1;
        if (kt < 127) {
            av = *(const float4*)(aptr + (kt + 1) * 8);
            bv = *(const float4*)(bptr + (kt + 1) * 8);
        }
#pragma unroll
        for (int k = 0; k < 8; k++) {
            float a[8], b[8];
            *(float4*)&a[0] = *(const float4*)&As[cur][k][ty * 8];
            *(float4*)&a[4] = *(const float4*)&As[cur][k][ty * 8 + 4];
            *(float4*)&b[0] = *(const float4*)&Bs[cur][k][tx * 8];
            *(float4*)&b[4] = *(const float4*)&Bs[cur][k][tx * 8 + 4];
#pragma unroll
            for (int i = 0; i < 8; i++)
#pragma unroll
                for (int j = 0; j < 8; j++) acc[i][j] += a[i] * b[j];
        }
        if (kt < 127) {
            int nb = cur ^ 1;
            As[nb][c + 0][row] = av.x; As[nb][c + 1][row] = av.y;
            As[nb][c + 2][row] = av.z; As[nb][c + 3][row] = av.w;
            Bs[nb][c + 0][row] = bv.x; Bs[nb][c + 1][row] = bv.y;
            Bs[nb][c + 2][row] = bv.z; Bs[nb][c + 3][row] = bv.w;
        }
        __syncthreads();
    }
#pragma unroll
    for (int i = 0; i < 8; i++) {
        int m = m0 + ty * 8 + i;
        int bb = m >> 9;
        int t  = m & 511;
        float* dst = g_Gx + ((size_t)t * BB + bb) * G3 + j0 + tx * 8;
#pragma unroll
        for (int j = 0; j < 8; j++)
            dst[j] = acc[i][j] + bih[j0 + tx * 8 + j];
    }
}

// ---------------- software grid barrier -------------------------------------
__device__ __forceinline__ void gsync(unsigned target) {
    __syncthreads();
    if (threadIdx.x == 0) {
        __threadfence();
        if (atomicAdd(&g_cnt, 1u) == GRID - 1u) {
            g_cnt = 0u;
            __threadfence();
            atomicExch(&g_epoch, target);
        } else {
            while (*(volatile unsigned*)&g_epoch < target) { __nanosleep(64); }
        }
        __threadfence();
    }
    __syncthreads();
}

// ---------------- persistent sequence kernel --------------------------------
// 128 blocks x 512 threads. Phase A: 32b x 96j tile via mma.sync bf16 hi/lo.
__global__ void __launch_bounds__(NTHR, 1)
k_seq(const float* __restrict__ bhh,
      const float* __restrict__ W1, const float* __restrict__ b1,
      const float* __restrict__ W2, const float* __restrict__ b2,
      float* __restrict__ out)
{
    extern __shared__ char dsm[];
    float* shf = (float*)dsm;
    const int tid = threadIdx.x;
    const int blk = blockIdx.x;
    unsigned bar = 1;

    uint32_t sbase;
    asm("{ .reg .u64 t; cvta.to.shared.u64 t, %1; cvt.u32.u64 %0, t; }"
        : "=r"(sbase) : "l"(dsm));

    const int a_b0 = (blk >> 5) * 32;
    const int a_i0 = (blk & 31) * 32;

    // ---- mma warp mapping (warps 0-7 compute; all 16 warps load) ----
    const int wid = tid >> 5, lane = tid & 31;
    const bool mmaw = (wid < 8);
    const int mt = wid & 1;             // m-tile (16 rows)
    const int np = wid >> 1;            // n-group: 24 j-cols
    // ldmatrix per-lane byte offsets (relative to region base, before ks*32)
    const int aoff = ((mt * 16 + (lane & 7) + ((lane & 8) ? 8 : 0)) * 72 +
                      ((lane & 16) ? 8 : 0)) * 2;
    const int boff4 = ((np * 24 + (lane & 7) + ((lane & 16) ? 8 : 0)) * 72 +
                       ((lane & 8) ? 8 : 0)) * 2;
    const int boff2 = ((np * 24 + 16 + (lane & 7)) * 72 +
                       ((lane & 8) ? 8 : 0)) * 2;

    // ---- A loader: 1 float4 per thread per chunk ----
    const int l_arow = tid >> 4;        // 0..31
    const int l_af4  = tid & 15;        // 0..15
    const int a_dst  = l_arow * 144 + l_af4 * 8;

    // ---- B loader: 3 uint4 per thread per chunk ----
    const __nv_bfloat16* b_basep[3];
    size_t b_off[3];
    int b_dst[3];
#pragma unroll
    for (int q = 0; q < 3; q++) {
        int idx = tid + 512 * q;
        bool hi = idx < 768;
        int idx2 = hi ? idx : idx - 768;
        int row = idx2 >> 3, seg = idx2 & 7;
        int jg = a_i0 + (row < 32 ? row : row < 64 ? 992 + row : 1984 + row);
        b_basep[q] = hi ? g_Bhi : g_Blo;
        b_off[q] = (size_t)jg * KTOT + seg * 8;
        b_dst[q] = (hi ? B_HI : B_LO) + row * 144 + seg * 16;
    }

    // Phase B/C mapping
    const int g  = tid >> 8;
    const int t2 = tid & 255;

    for (int t = 0; t < TT; t++) {
        const float* hcur = g_hbuf[t & 1];
        float* hnxt = g_hbuf[(t & 1) ^ 1];

        // ================= Phase A: mma.sync bf16-split GEMM ===============
        float cH[3][4] = {}, cS[3][4] = {};
        float4 aP;
        uint4 bP0, bP1, bP2;

        // prefetch chunk 0
        aP = *(const float4*)(hcur + (size_t)(a_b0 + l_arow) * HH + l_af4 * 4);
        bP0 = *(const uint4*)(b_basep[0] + b_off[0]);
        bP1 = *(const uint4*)(b_basep[1] + b_off[1]);
        bP2 = *(const uint4*)(b_basep[2] + b_off[2]);
        {
            uint32_t h01, l01, h23, l23;
            split2(aP.x, aP.y, h01, l01);
            split2(aP.z, aP.w, h23, l23);
            *(uint2*)(dsm + A_HI + a_dst) = make_uint2(h01, h23);
            *(uint2*)(dsm + A_LO + a_dst) = make_uint2(l01, l23);
            *(uint4*)(dsm + b_dst[0]) = bP0;
            *(uint4*)(dsm + b_dst[1]) = bP1;
            *(uint4*)(dsm + b_dst[2]) = bP2;
        }
        __syncthreads();

        for (int c = 0; c < NCH; c++) {
            const uint32_t bufs = sbase + (c & 1) * BUF_BYTES;
            // prefetch next chunk to regs
            if (c < NCH - 1) {
                int cn = c + 1;
                const float* asrc = (cn < 16)
                    ? (hcur + (size_t)(a_b0 + l_arow) * HH + cn * 64 + l_af4 * 4)
                    : (g_state + (size_t)(a_b0 + l_arow) * KK + l_af4 * 4);
                aP = *(const float4*)asrc;
                bP0 = *(const uint4*)(b_basep[0] + b_off[0] + cn * 64);
                bP1 = *(const uint4*)(b_basep[1] + b_off[1] + cn * 64);
                bP2 = *(const uint4*)(b_basep[2] + b_off[2] + cn * 64);
            }
            // mma on current buffer
            if (mmaw) {
                float (*cc)[4] = (c == 16) ? cS : cH;
#pragma unroll
                for (int ks = 0; ks < 4; ks++) {
                    uint32_t ah0, ah1, ah2, ah3, al0, al1, al2, al3;
                    ldm4(ah0, ah1, ah2, ah3, bufs + A_HI + aoff + ks * 32);
                    ldm4(al0, al1, al2, al3, bufs + A_LO + aoff + ks * 32);
                    uint32_t bh0, bh1, bh2, bh3, bh4, bh5;
                    ldm4(bh0, bh1, bh2, bh3, bufs + B_HI + boff4 + ks * 32);
                    ldm2(bh4, bh5,           bufs + B_HI + boff2 + ks * 32);
                    uint32_t bl0, bl1, bl2, bl3, bl4, bl5;
                    ldm4(bl0, bl1, bl2, bl3, bufs + B_LO + boff4 + ks * 32);
                    ldm2(bl4, bl5,           bufs + B_LO + boff2 + ks * 32);
                    mma_bf16(cc[0], ah0, ah1, ah2, ah3, bh0, bh1);
                    mma_bf16(cc[0], ah0, ah1, ah2, ah3, bl0, bl1);
                    mma_bf16(cc[0], al0, al1, al2, al3, bh0, bh1);
                    mma_bf16(cc[1], ah0, ah1, ah2, ah3, bh2, bh3);
                    mma_bf16(cc[1], ah0, ah1, ah2, ah3, bl2, bl3);
                    mma_bf16(cc[1], al0, al1, al2, al3, bh2, bh3);
                    mma_bf16(cc[2], ah0, ah1, ah2, ah3, bh4, bh5);
                    mma_bf16(cc[2], ah0, ah1, ah2, ah3, bl4, bl5);
                    mma_bf16(cc[2], al0, al1, al2, al3, bh4, bh5);
                }
            }
            // store prefetched regs into the other buffer
            if (c < NCH - 1) {
                char* nb = dsm + ((c + 1) & 1) * BUF_BYTES;
                uint32_t h01, l01, h23, l23;
                split2(aP.x, aP.y, h01, l01);
                split2(aP.z, aP.w, h23, l23);
                *(uint2*)(nb + A_HI + a_dst) = make_uint2(h01, h23);
                *(uint2*)(nb + A_LO + a_dst) = make_uint2(l01, l23);
                *(uint4*)(nb + b_dst[0]) = bP0;
                *(uint4*)(nb + b_dst[1]) = bP1;
                *(uint4*)(nb + b_dst[2]) = bP2;
            }
            __syncthreads();
        }

        // ---- stage fragments: preH/preS [96][33] floats ----
        {
            float* preH = shf;
            float* preS = shf + 96 * 33;
            if (mmaw) {
                const int rb = mt * 16 + (lane >> 2);
#pragma unroll
                for (int tau = 0; tau < 3; tau++) {
                    int jc = np * 24 + tau * 8 + (lane & 3) * 2;
                    preH[jc * 33 + rb]           = cH[tau][0];
                    preH[(jc + 1) * 33 + rb]     = cH[tau][1];
                    preH[jc * 33 + rb + 8]       = cH[tau][2];
                    preH[(jc + 1) * 33 + rb + 8] = cH[tau][3];
                    preS[jc * 33 + rb]           = cS[tau][0];
                    preS[(jc + 1) * 33 + rb]     = cS[tau][1];
                    preS[jc * 33 + rb + 8]       = cS[tau][2];
                    preS[(jc + 1) * 33 + rb + 8] = cS[tau][3];
                }
            }
            __syncthreads();

            // ---- gate epilogue -> h_new (block-local) ----
            const float* gx = g_Gx + ((size_t)t * BB + a_b0) * G3;
#pragma unroll
            for (int rep = 0; rep < 2; rep++) {
                int idx = tid + rep * 512;
                int b = idx >> 5, i = idx & 31;
                int ii = a_i0 + i;
                const float* gxb = gx + (size_t)b * G3;
                float Sr = preH[i * 33 + b] + preS[i * 33 + b] + gxb[ii] + bhh[ii];
                float Sz = preH[(32 + i) * 33 + b] + preS[(32 + i) * 33 + b] +
                           gxb[1024 + ii] + bhh[1024 + ii];
                float An = preS[(64 + i) * 33 + b] + gxb[2048 + ii];
                float Hn = preH[(64 + i) * 33 + b] + bhh[2048 + ii];
                float r = 1.0f / (1.0f + expf(-Sr));
                float z = 1.0f / (1.0f + expf(-Sz));
                float n = tanhf(An + r * Hn);
                hnxt[(size_t)(a_b0 + b) * HH + ii] =
                    (1.0f - z) * n + z * hcur[(size_t)(a_b0 + b) * HH + ii];
            }
        }
        gsync(bar++);

        // ========== Phase B: a1 = tanh(h_new @ W1^T + b1), split-k x2 ======
        {
            const int b_o0 = (blk & 31) * 16;
            const int bty = t2 >> 3;
            const int btx = t2 & 7;
            const int lr = t2 >> 2, lc = (t2 & 3) * 4;
            float c0 = 0.0f, c1 = 0.0f;
            for (int kt = 0; kt < 32; kt++) {
                int k0 = g * 512 + kt * 16;
                if (t2 < 128) {
                    float4 v = *(const float4*)&hnxt[(size_t)(a_b0 + lr) * HH + k0 + lc];
                    shf[g * 512 + (lc + 0) * 32 + lr] = v.x;
                    shf[g * 512 + (lc + 1) * 32 + lr] = v.y;
                    shf[g * 512 + (lc + 2) * 32 + lr] = v.z;
                    shf[g * 512 + (lc + 3) * 32 + lr] = v.w;
                }
                if (t2 < 64) {
                    int row = t2 >> 2, c = (t2 & 3) * 4;
                    float4 w = *(const float4*)&W1[(size_t)(b_o0 + row) * HH + k0 + c];
                    shf[1024 + g * 256 + (c + 0) * 16 + row] = w.x;
                    shf[1024 + g * 256 + (c + 1) * 16 + row] = w.y;
                    shf[1024 + g * 256 + (c + 2) * 16 + row] = w.z;
                    shf[1024 + g * 256 + (c + 3) * 16 + row] = w.w;
                }
                __syncthreads();
#pragma unroll
                for (int k = 0; k < 16; k++) {
                    float a = shf[g * 512 + k * 32 + bty];
                    float2 w = *(const float2*)&shf[1024 + g * 256 + k * 16 + btx * 2];
                    c0 += a * w.x; c1 += a * w.y;
                }
                __syncthreads();
            }
            if (g == 1) {
                shf[2048 + t2 * 2] = c0; shf[2048 + t2 * 2 + 1] = c1;
            }
            __syncthreads();
            if (g == 0) {
                c0 += shf[2048 + t2 * 2]; c1 += shf[2048 + t2 * 2 + 1];
                int b = a_b0 + bty, o = b_o0 + btx * 2;
                g_a1[b * HIDV + o]     = tanhf(c0 + b1[o]);
                g_a1[b * HIDV + o + 1] = tanhf(c1 + b1[o + 1]);
            }
        }
        gsync(bar++);

        // ========== Phase C: logits + softmax state, split-k x8 ============
        {
            int b = blk;
            shf[tid] = g_a1[b * HIDV + tid];
            __syncthreads();
            int k = tid & 63, q = tid >> 6;
            const float* w = W2 + (size_t)k * HIDV + q * 64;
            const float* a = shf + q * 64;
            float p = 0.0f;
#pragma unroll 16
            for (int i = 0; i < 64; i++) p += a[i] * w[i];
            shf[512 + tid] = p;
            __syncthreads();
            if (tid < KK) {
                float lg = b2[tid];
#pragma unroll
                for (int q2 = 0; q2 < 8; q2++) lg += shf[512 + q2 * 64 + tid];
                out[((size_t)b * TT + t) * KK + tid] = lg;
                shf[1024 + tid] = fminf(fmaxf(lg, -10.0f), 10.0f);
            }
            __syncthreads();
            if (tid < 32) {
                float x0 = shf[1024 + tid], x1 = shf[1024 + tid + 32];
                float m = fmaxf(x0, x1);
#pragma unroll
                for (int o = 16; o; o >>= 1) m = fmaxf(m, __shfl_xor_sync(0xffffffffu, m, o));
                float e0 = expf(x0 - m), e1 = expf(x1 - m);
                float s = e0 + e1;
#pragma unroll
                for (int o = 16; o; o >>= 1) s += __shfl_xor_sync(0xffffffffu, s, o);
                float inv = 1.0f / s;
                g_state[b * KK + tid]      = e0 * inv;
                g_state[b * KK + tid + 32] = e1 * inv;
            }
        }
        gsync(bar++);
    }
}

// ---------------- host launch -----------------------------------------------
extern "C" void kernel_launch(void* const* d_in, const int* in_sizes, int n_in,
                              void* d_out, int out_size) {
    const float* ctx  = (const float*)d_in[0];   // [B,T,H]
    const float* init = (const float*)d_in[1];   // [B,K]
    const float* E    = (const float*)d_in[2];   // [K,S]
    const float* Wih  = (const float*)d_in[3];   // [3H,D]
    const float* Whh  = (const float*)d_in[4];   // [3H,H]
    const float* bih  = (const float*)d_in[5];   // [3H]
    const float* bhh  = (const float*)d_in[6];   // [3H]
    const float* W1   = (const float*)d_in[7];   // [HID,H]
    const float* b1   = (const float*)d_in[8];   // [HID]
    const float* W2   = (const float*)d_in[9];   // [K,HID]
    const float* b2   = (const float*)d_in[10];  // [K]
    float* out = (float*)d_out;                  // [B,T,K] fp32

    cudaFuncSetAttribute(k_seq, cudaFuncAttributeMaxDynamicSharedMemorySize, SMEM_DYN);

    k_init<<<512, 256>>>(init);
    k_prep<<<G3, 128>>>(Whh, E, Wih);
    k_gx<<<dim3(G3 / 128, (BB * TT) / 128), 256>>>(ctx, Wih, bih);
    k_seq<<<GRID, NTHR, SMEM_DYN>>>(bhh, W1, b1, W2, b2, out);
}

// round 12
// speedup vs baseline: 2.2796x; 1.1738x over previous
#include <cuda_runtime.h>
#include <cuda_bf16.h>
#include <math.h>
#include <stdint.h>

#define BB 128
#define TT 512
#define HH 1024
#define SS 128
#define KK 64
#define HIDV 512
#define DD 1152
#define G3 3072
#define GRID 128
#define NTHR 512
#define KTOT 1088
#define NCH 17
// k_seq smem byte offsets (stride 72 bf16 = 144 B rows)
#define A_HI 0
#define A_LO 4608
#define B_HI 9216
#define B_LO 23040
#define BUF_BYTES 36864
#define SMEM_DYN (2 * BUF_BYTES)
// k_gx smem offsets (stride 24 bf16 = 48 B rows), buffer = 24576 B
#define GA_HI 0
#define GA_LO 6144
#define GB_HI 12288
#define GB_LO 18432
#define GBUF 24576

// ---------------- scratch (device globals; no allocation allowed) ----------
__device__ float g_Gx[(size_t)TT * BB * G3];                 // [t][b][3H]
__device__ float g_hbuf[2][BB * HH];
__device__ float g_state[BB * KK];
__device__ float g_a1[BB * HIDV];
__device__ __align__(16) __nv_bfloat16 g_Bhi[(size_t)G3 * KTOT];
__device__ __align__(16) __nv_bfloat16 g_Blo[(size_t)G3 * KTOT];
__device__ __align__(16) __nv_bfloat16 g_Whi[(size_t)G3 * HH];
__device__ __align__(16) __nv_bfloat16 g_Wlo[(size_t)G3 * HH];
__device__ unsigned g_cnt;
__device__ unsigned g_epoch;

// ---------------- mma/ldmatrix helpers (sm_80-era PTX, compiles compute_103)
__device__ __forceinline__ void ldm4(uint32_t& r0, uint32_t& r1, uint32_t& r2,
                                     uint32_t& r3, uint32_t a) {
    asm volatile("ldmatrix.sync.aligned.m8n8.x4.shared.b16 {%0,%1,%2,%3}, [%4];"
                 : "=r"(r0), "=r"(r1), "=r"(r2), "=r"(r3) : "r"(a));
}
__device__ __forceinline__ void ldm2(uint32_t& r0, uint32_t& r1, uint32_t a) {
    asm volatile("ldmatrix.sync.aligned.m8n8.x2.shared.b16 {%0,%1}, [%2];"
                 : "=r"(r0), "=r"(r1) : "r"(a));
}
__device__ __forceinline__ void mma_bf16(float* c, uint32_t a0, uint32_t a1,
                                         uint32_t a2, uint32_t a3,
                                         uint32_t b0, uint32_t b1) {
    asm volatile("mma.sync.aligned.m16n8k16.row.col.f32.bf16.bf16.f32 "
                 "{%0,%1,%2,%3}, {%4,%5,%6,%7}, {%8,%9}, {%0,%1,%2,%3};"
                 : "+f"(c[0]), "+f"(c[1]), "+f"(c[2]), "+f"(c[3])
                 : "r"(a0), "r"(a1), "r"(a2), "r"(a3), "r"(b0), "r"(b1));
}
static __device__ __forceinline__ void split2(float a, float b,
                                              uint32_t& whi, uint32_t& wlo) {
    __nv_bfloat16 ha = __float2bfloat16(a), hb = __float2bfloat16(b);
    __nv_bfloat16 la = __float2bfloat16(a - __bfloat162float(ha));
    __nv_bfloat16 lb = __float2bfloat16(b - __bfloat162float(hb));
    whi = (uint32_t)__bfloat16_as_ushort(ha) | ((uint32_t)__bfloat16_as_ushort(hb) << 16);
    wlo = (uint32_t)__bfloat16_as_ushort(la) | ((uint32_t)__bfloat16_as_ushort(lb) << 16);
}

// ---------------- init ------------------------------------------------------
__global__ void k_init(const float* __restrict__ init_state) {
    int idx = blockIdx.x * blockDim.x + threadIdx.x;
    if (idx < BB * HH) g_hbuf[0][idx] = 0.0f;
    if (idx < BB * KK) g_state[idx] = init_state[idx];
    if (idx == 0) { g_cnt = 0u; g_epoch = 0u; }
}

// ---------------- k_prep: build B = [Whh | Mse^T] as bf16 hi/lo -------------
__global__ void k_prep(const float* __restrict__ Whh, const float* __restrict__ E,
                       const float* __restrict__ Wih) {
    int j = blockIdx.x;
    __shared__ float ws[SS];
    ws[threadIdx.x] = Wih[(size_t)j * DD + HH + threadIdx.x];
    __syncthreads();
    for (int col = threadIdx.x; col < KTOT; col += 128) {
        float v;
        if (col < HH) v = Whh[(size_t)j * HH + col];
        else {
            int kk = col - HH;
            float a = 0.0f;
#pragma unroll 8
            for (int s = 0; s < SS; s++) a += E[kk * SS + s] * ws[s];
            v = a;
        }
        __nv_bfloat16 hi = __float2bfloat16(v);
        __nv_bfloat16 lo = __float2bfloat16(v - __bfloat162float(hi));
        g_Bhi[(size_t)j * KTOT + col] = hi;
        g_Blo[(size_t)j * KTOT + col] = lo;
    }
}

// ---------------- k_prepw: split W_ih[:, :H] into bf16 hi/lo ----------------
__global__ void k_prepw(const float* __restrict__ Wih) {
    int j = blockIdx.x;
    for (int col = threadIdx.x; col < HH; col += 256) {
        float v = Wih[(size_t)j * DD + col];
        __nv_bfloat16 hi = __float2bfloat16(v);
        __nv_bfloat16 lo = __float2bfloat16(v - __bfloat162float(hi));
        g_Whi[(size_t)j * HH + col] = hi;
        g_Wlo[(size_t)j * HH + col] = lo;
    }
}

// ---------------- Gx = contexts @ W_ih[:, :H]^T + b_ih (bf16 hi/lo mma) -----
// block tile 128x128, K=16 chunks double-buffered; 8 warps, warp tile 32x64.
__global__ void __launch_bounds__(256, 2)
k_gx(const float* __restrict__ ctx, const float* __restrict__ bih) {
    __shared__ __align__(16) char sm[2][GBUF];
    const int tid = threadIdx.x, wid = tid >> 5, lane = tid & 31;
    const int m0 = blockIdx.y * 128, j0 = blockIdx.x * 128;
    const int wm = wid & 3, wn = wid >> 2;

    uint32_t sb;
    asm("{ .reg .u64 t; cvta.to.shared.u64 t, %1; cvt.u32.u64 %0, t; }"
        : "=r"(sb) : "l"((void*)sm));

    // loaders: 2 threads per row, 8 cols each
    const int lr = tid >> 1;
    const int lc8 = (tid & 1) * 8;
    const float* actx = ctx + (size_t)(m0 + lr) * HH + lc8;
    const __nv_bfloat16* wh = g_Whi + (size_t)(j0 + lr) * HH + lc8;
    const __nv_bfloat16* wl = g_Wlo + (size_t)(j0 + lr) * HH + lc8;
    const int adst = lr * 48 + (tid & 1) * 16;

    // ldmatrix byte offsets
    int aoff[2], boff[4];
#pragma unroll
    for (int mt = 0; mt < 2; mt++)
        aoff[mt] = (wm * 32 + mt * 16 + (lane & 7) + ((lane & 8) ? 8 : 0)) * 48 +
                   ((lane & 16) ? 16 : 0);
#pragma unroll
    for (int nb = 0; nb < 4; nb++)
        boff[nb] = (wn * 64 + nb * 16 + (lane & 7) + ((lane & 16) ? 8 : 0)) * 48 +
                   ((lane & 8) ? 16 : 0);

    float acc[2][8][4];
#pragma unroll
    for (int i = 0; i < 2; i++)
#pragma unroll
        for (int j = 0; j < 8; j++)
#pragma unroll
            for (int q = 0; q < 4; q++) acc[i][j][q] = 0.0f;

    float4 v0, v1;
    uint4 bhv, blv;

    // prologue: chunk 0 -> buffer 0
    v0 = *(const float4*)(actx);
    v1 = *(const float4*)(actx + 4);
    bhv = *(const uint4*)(wh);
    blv = *(const uint4*)(wl);
    {
        uint32_t h0, l0, h1, l1, h2, l2, h3, l3;
        split2(v0.x, v0.y, h0, l0); split2(v0.z, v0.w, h1, l1);
        split2(v1.x, v1.y, h2, l2); split2(v1.z, v1.w, h3, l3);
        *(uint4*)(sm[0] + GA_HI + adst) = make_uint4(h0, h1, h2, h3);
        *(uint4*)(sm[0] + GA_LO + adst) = make_uint4(l0, l1, l2, l3);
        *(uint4*)(sm[0] + GB_HI + adst) = bhv;
        *(uint4*)(sm[0] + GB_LO + adst) = blv;
    }
    __syncthreads();

    for (int c = 0; c < 64; c++) {
        if (c < 63) {
            int k0 = (c + 1) * 16;
            v0 = *(const float4*)(actx + k0);
            v1 = *(const float4*)(actx + k0 + 4);
            bhv = *(const uint4*)(wh + k0);
            blv = *(const uint4*)(wl + k0);
        }
        const uint32_t bufs = sb + (c & 1) * GBUF;
#pragma unroll
        for (int mt = 0; mt < 2; mt++) {
            uint32_t ah0, ah1, ah2, ah3, al0, al1, al2, al3;
            ldm4(ah0, ah1, ah2, ah3, bufs + GA_HI + aoff[mt]);
            ldm4(al0, al1, al2, al3, bufs + GA_LO + aoff[mt]);
#pragma unroll
            for (int nb = 0; nb < 4; nb++) {
                uint32_t bh0, bh1, bh2, bh3, bl0, bl1, bl2, bl3;
                ldm4(bh0, bh1, bh2, bh3, bufs + GB_HI + boff[nb]);
                ldm4(bl0, bl1, bl2, bl3, bufs + GB_LO + boff[nb]);
                float* c0 = acc[mt][nb * 2];
                float* c1 = acc[mt][nb * 2 + 1];
                mma_bf16(c0, ah0, ah1, ah2, ah3, bh0, bh1);
                mma_bf16(c0, ah0, ah1, ah2, ah3, bl0, bl1);
                mma_bf16(c0, al0, al1, al2, al3, bh0, bh1);
                mma_bf16(c1, ah0, ah1, ah2, ah3, bh2, bh3);
                mma_bf16(c1, ah0, ah1, ah2, ah3, bl2, bl3);
                mma_bf16(c1, al0, al1, al2, al3, bh2, bh3);
            }
        }
        if (c < 63) {
            char* nb2 = sm[(c + 1) & 1];
            uint32_t h0, l0, h1, l1, h2, l2, h3, l3;
            split2(v0.x, v0.y, h0, l0); split2(v0.z, v0.w, h1, l1);
            split2(v1.x, v1.y, h2, l2); split2(v1.z, v1.w, h3, l3);
            *(uint4*)(nb2 + GA_HI + adst) = make_uint4(h0, h1, h2, h3);
            *(uint4*)(nb2 + GA_LO + adst) = make_uint4(l0, l1, l2, l3);
            *(uint4*)(nb2 + GB_HI + adst) = bhv;
            *(uint4*)(nb2 + GB_LO + adst) = blv;
        }
        __syncthreads();
    }

    // epilogue: scatter to [t][b][3H] with bias
#pragma unroll
    for (int mt = 0; mt < 2; mt++) {
#pragma unroll
        for (int nt = 0; nt < 8; nt++) {
            int col = j0 + wn * 64 + nt * 8 + (lane & 3) * 2;
            float bi0 = bih[col], bi1 = bih[col + 1];
#pragma unroll
            for (int rr = 0; rr < 2; rr++) {
                int m = m0 + wm * 32 + mt * 16 + (lane >> 2) + rr * 8;
                int bb = m >> 9, tt = m & 511;
                float2 val = make_float2(acc[mt][nt][rr * 2] + bi0,
                                         acc[mt][nt][rr * 2 + 1] + bi1);
                *(float2*)(g_Gx + ((size_t)tt * BB + bb) * G3 + col) = val;
            }
        }
    }
}

// ---------------- software grid barrier -------------------------------------
__device__ __forceinline__ void gsync(unsigned target) {
    __syncthreads();
    if (threadIdx.x == 0) {
        __threadfence();
        if (atomicAdd(&g_cnt, 1u) == GRID - 1u) {
            g_cnt = 0u;
            __threadfence();
            atomicExch(&g_epoch, target);
        } else {
            while (*(volatile unsigned*)&g_epoch < target) { __nanosleep(64); }
        }
        __threadfence();
    }
    __syncthreads();
}

// ---------------- persistent sequence kernel (identical to R11) -------------
__global__ void __launch_bounds__(NTHR, 1)
k_seq(const float* __restrict__ bhh,
      const float* __restrict__ W1, const float* __restrict__ b1,
      const float* __restrict__ W2, const float* __restrict__ b2,
      float* __restrict__ out)
{
    extern __shared__ char dsm[];
    float* shf = (float*)dsm;
    const int tid = threadIdx.x;
    const int blk = blockIdx.x;
    unsigned bar = 1;

    uint32_t sbase;
    asm("{ .reg .u64 t; cvta.to.shared.u64 t, %1; cvt.u32.u64 %0, t; }"
        : "=r"(sbase) : "l"(dsm));

    const int a_b0 = (blk >> 5) * 32;
    const int a_i0 = (blk & 31) * 32;

    const int wid = tid >> 5, lane = tid & 31;
    const bool mmaw = (wid < 8);
    const int mt = wid & 1;
    const int np = wid >> 1;
    const int aoff = ((mt * 16 + (lane & 7) + ((lane & 8) ? 8 : 0)) * 72 +
                      ((lane & 16) ? 8 : 0)) * 2;
    const int boff4 = ((np * 24 + (lane & 7) + ((lane & 16) ? 8 : 0)) * 72 +
                       ((lane & 8) ? 8 : 0)) * 2;
    const int boff2 = ((np * 24 + 16 + (lane & 7)) * 72 +
                       ((lane & 8) ? 8 : 0)) * 2;

    const int l_arow = tid >> 4;
    const int l_af4  = tid & 15;
    const int a_dst  = l_arow * 144 + l_af4 * 8;

    const __nv_bfloat16* b_basep[3];
    size_t b_off[3];
    int b_dst[3];
#pragma unroll
    for (int q = 0; q < 3; q++) {
        int idx = tid + 512 * q;
        bool hi = idx < 768;
        int idx2 = hi ? idx : idx - 768;
        int row = idx2 >> 3, seg = idx2 & 7;
        int jg = a_i0 + (row < 32 ? row : row < 64 ? 992 + row : 1984 + row);
        b_basep[q] = hi ? g_Bhi : g_Blo;
        b_off[q] = (size_t)jg * KTOT + seg * 8;
        b_dst[q] = (hi ? B_HI : B_LO) + row * 144 + seg * 16;
    }

    const int g  = tid >> 8;
    const int t2 = tid & 255;

    for (int t = 0; t < TT; t++) {
        const float* hcur = g_hbuf[t & 1];
        float* hnxt = g_hbuf[(t & 1) ^ 1];

        float cH[3][4] = {}, cS[3][4] = {};
        float4 aP;
        uint4 bP0, bP1, bP2;

        aP = *(const float4*)(hcur + (size_t)(a_b0 + l_arow) * HH + l_af4 * 4);
        bP0 = *(const uint4*)(b_basep[0] + b_off[0]);
        bP1 = *(const uint4*)(b_basep[1] + b_off[1]);
        bP2 = *(const uint4*)(b_basep[2] + b_off[2]);
        {
            uint32_t h01, l01, h23, l23;
            split2(aP.x, aP.y, h01, l01);
            split2(aP.z, aP.w, h23, l23);
            *(uint2*)(dsm + A_HI + a_dst) = make_uint2(h01, h23);
            *(uint2*)(dsm + A_LO + a_dst) = make_uint2(l01, l23);
            *(uint4*)(dsm + b_dst[0]) = bP0;
            *(uint4*)(dsm + b_dst[1]) = bP1;
            *(uint4*)(dsm + b_dst[2]) = bP2;
        }
        __syncthreads();

        for (int c = 0; c < NCH; c++) {
            const uint32_t bufs = sbase + (c & 1) * BUF_BYTES;
            if (c < NCH - 1) {
                int cn = c + 1;
                const float* asrc = (cn < 16)
                    ? (hcur + (size_t)(a_b0 + l_arow) * HH + cn * 64 + l_af4 * 4)
                    : (g_state + (size_t)(a_b0 + l_arow) * KK + l_af4 * 4);
                aP = *(const float4*)asrc;
                bP0 = *(const uint4*)(b_basep[0] + b_off[0] + cn * 64);
                bP1 = *(const uint4*)(b_basep[1] + b_off[1] + cn * 64);
                bP2 = *(const uint4*)(b_basep[2] + b_off[2] + cn * 64);
            }
            if (mmaw) {
                float (*cc)[4] = (c == 16) ? cS : cH;
#pragma unroll
                for (int ks = 0; ks < 4; ks++) {
                    uint32_t ah0, ah1, ah2, ah3, al0, al1, al2, al3;
                    ldm4(ah0, ah1, ah2, ah3, bufs + A_HI + aoff + ks * 32);
                    ldm4(al0, al1, al2, al3, bufs + A_LO + aoff + ks * 32);
                    uint32_t bh0, bh1, bh2, bh3, bh4, bh5;
                    ldm4(bh0, bh1, bh2, bh3, bufs + B_HI + boff4 + ks * 32);
                    ldm2(bh4, bh5,           bufs + B_HI + boff2 + ks * 32);
                    uint32_t bl0, bl1, bl2, bl3, bl4, bl5;
                    ldm4(bl0, bl1, bl2, bl3, bufs + B_LO + boff4 + ks * 32);
                    ldm2(bl4, bl5,           bufs + B_LO + boff2 + ks * 32);
                    mma_bf16(cc[0], ah0, ah1, ah2, ah3, bh0, bh1);
                    mma_bf16(cc[0], ah0, ah1, ah2, ah3, bl0, bl1);
                    mma_bf16(cc[0], al0, al1, al2, al3, bh0, bh1);
                    mma_bf16(cc[1], ah0, ah1, ah2, ah3, bh2, bh3);
                    mma_bf16(cc[1], ah0, ah1, ah2, ah3, bl2, bl3);
                    mma_bf16(cc[1], al0, al1, al2, al3, bh2, bh3);
                    mma_bf16(cc[2], ah0, ah1, ah2, ah3, bh4, bh5);
                    mma_bf16(cc[2], ah0, ah1, ah2, ah3, bl4, bl5);
                    mma_bf16(cc[2], al0, al1, al2, al3, bh4, bh5);
                }
            }
            if (c < NCH - 1) {
                char* nb = dsm + ((c + 1) & 1) * BUF_BYTES;
                uint32_t h01, l01, h23, l23;
                split2(aP.x, aP.y, h01, l01);
                split2(aP.z, aP.w, h23, l23);
                *(uint2*)(nb + A_HI + a_dst) = make_uint2(h01, h23);
                *(uint2*)(nb + A_LO + a_dst) = make_uint2(l01, l23);
                *(uint4*)(nb + b_dst[0]) = bP0;
                *(uint4*)(nb + b_dst[1]) = bP1;
                *(uint4*)(nb + b_dst[2]) = bP2;
            }
            __syncthreads();
        }

        {
            float* preH = shf;
            float* preS = shf + 96 * 33;
            if (mmaw) {
                const int rb = mt * 16 + (lane >> 2);
#pragma unroll
                for (int tau = 0; tau < 3; tau++) {
                    int jc = np * 24 + tau * 8 + (lane & 3) * 2;
                    preH[jc * 33 + rb]           = cH[tau][0];
                    preH[(jc + 1) * 33 + rb]     = cH[tau][1];
                    preH[jc * 33 + rb + 8]       = cH[tau][2];
                    preH[(jc + 1) * 33 + rb + 8] = cH[tau][3];
                    preS[jc * 33 + rb]           = cS[tau][0];
                    preS[(jc + 1) * 33 + rb]     = cS[tau][1];
                    preS[jc * 33 + rb + 8]       = cS[tau][2];
                    preS[(jc + 1) * 33 + rb + 8] = cS[tau][3];
                }
            }
            __syncthreads();

            const float* gx = g_Gx + ((size_t)t * BB + a_b0) * G3;
#pragma unroll
            for (int rep = 0; rep < 2; rep++) {
                int idx = tid + rep * 512;
                int b = idx >> 5, i = idx & 31;
                int ii = a_i0 + i;
                const float* gxb = gx + (size_t)b * G3;
                float Sr = preH[i * 33 + b] + preS[i * 33 + b] + gxb[ii] + bhh[ii];
                float Sz = preH[(32 + i) * 33 + b] + preS[(32 + i) * 33 + b] +
                           gxb[1024 + ii] + bhh[1024 + ii];
                float An = preS[(64 + i) * 33 + b] + gxb[2048 + ii];
                float Hn = preH[(64 + i) * 33 + b] + bhh[2048 + ii];
                float r = 1.0f / (1.0f + expf(-Sr));
                float z = 1.0f / (1.0f + expf(-Sz));
                float n = tanhf(An + r * Hn);
                hnxt[(size_t)(a_b0 + b) * HH + ii] =
                    (1.0f - z) * n + z * hcur[(size_t)(a_b0 + b) * HH + ii];
            }
        }
        gsync(bar++);

        {
            const int b_o0 = (blk & 31) * 16;
            const int bty = t2 >> 3;
            const int btx = t2 & 7;
            const int lr = t2 >> 2, lc = (t2 & 3) * 4;
            float c0 = 0.0f, c1 = 0.0f;
            for (int kt = 0; kt < 32; kt++) {
                int k0 = g * 512 + kt * 16;
                if (t2 < 128) {
                    float4 v = *(const float4*)&hnxt[(size_t)(a_b0 + lr) * HH + k0 + lc];
                    shf[g * 512 + (lc + 0) * 32 + lr] = v.x;
                    shf[g * 512 + (lc + 1) * 32 + lr] = v.y;
                    shf[g * 512 + (lc + 2) * 32 + lr] = v.z;
                    shf[g * 512 + (lc + 3) * 32 + lr] = v.w;
                }
                if (t2 < 64) {
                    int row = t2 >> 2, c = (t2 & 3) * 4;
                    float4 w = *(const float4*)&W1[(size_t)(b_o0 + row) * HH + k0 + c];
                    shf[1024 + g * 256 + (c + 0) * 16 + row] = w.x;
                    shf[1024 + g * 256 + (c + 1) * 16 + row] = w.y;
                    shf[1024 + g * 256 + (c + 2) * 16 + row] = w.z;
                    shf[1024 + g * 256 + (c + 3) * 16 + row] = w.w;
                }
                __syncthreads();
#pragma unroll
                for (int k = 0; k < 16; k++) {
                    float a = shf[g * 512 + k * 32 + bty];
                    float2 w = *(const float2*)&shf[1024 + g * 256 + k * 16 + btx * 2];
                    c0 += a * w.x; c1 += a * w.y;
                }
                __syncthreads();
            }
            if (g == 1) {
                shf[2048 + t2 * 2] = c0; shf[2048 + t2 * 2 + 1] = c1;
            }
            __syncthreads();
            if (g == 0) {
                c0 += shf[2048 + t2 * 2]; c1 += shf[2048 + t2 * 2 + 1];
                int b = a_b0 + bty, o = b_o0 + btx * 2;
                g_a1[b * HIDV + o]     = tanhf(c0 + b1[o]);
                g_a1[b * HIDV + o + 1] = tanhf(c1 + b1[o + 1]);
            }
        }
        gsync(bar++);

        {
            int b = blk;
            shf[tid] = g_a1[b * HIDV + tid];
            __syncthreads();
            int k = tid & 63, q = tid >> 6;
            const float* w = W2 + (size_t)k * HIDV + q * 64;
            const float* a = shf + q * 64;
            float p = 0.0f;
#pragma unroll 16
            for (int i = 0; i < 64; i++) p += a[i] * w[i];
            shf[512 + tid] = p;
            __syncthreads();
            if (tid < KK) {
                float lg = b2[tid];
#pragma unroll
                for (int q2 = 0; q2 < 8; q2++) lg += shf[512 + q2 * 64 + tid];
                out[((size_t)b * TT + t) * KK + tid] = lg;
                shf[1024 + tid] = fminf(fmaxf(lg, -10.0f), 10.0f);
            }
            __syncthreads();
            if (tid < 32) {
                float x0 = shf[1024 + tid], x1 = shf[1024 + tid + 32];
                float m = fmaxf(x0, x1);
#pragma unroll
                for (int o = 16; o; o >>= 1) m = fmaxf(m, __shfl_xor_sync(0xffffffffu, m, o));
                float e0 = expf(x0 - m), e1 = expf(x1 - m);
                float s = e0 + e1;
#pragma unroll
                for (int o = 16; o; o >>= 1) s += __shfl_xor_sync(0xffffffffu, s, o);
                float inv = 1.0f / s;
                g_state[b * KK + tid]      = e0 * inv;
                g_state[b * KK + tid + 32] = e1 * inv;
            }
        }
        gsync(bar++);
    }
}

// ---------------- host launch -----------------------------------------------
extern "C" void kernel_launch(void* const* d_in, const int* in_sizes, int n_in,
                              void* d_out, int out_size) {
    const float* ctx  = (const float*)d_in[0];   // [B,T,H]
    const float* init = (const float*)d_in[1];   // [B,K]
    const float* E    = (const float*)d_in[2];   // [K,S]
    const float* Wih  = (const float*)d_in[3];   // [3H,D]
    const float* Whh  = (const float*)d_in[4];   // [3H,H]
    const float* bih  = (const float*)d_in[5];   // [3H]
    const float* bhh  = (const float*)d_in[6];   // [3H]
    const float* W1   = (const float*)d_in[7];   // [HID,H]
    const float* b1   = (const float*)d_in[8];   // [HID]
    const float* W2   = (const float*)d_in[9];   // [K,HID]
    const float* b2   = (const float*)d_in[10];  // [K]
    float* out = (float*)d_out;                  // [B,T,K] fp32

    cudaFuncSetAttribute(k_seq, cudaFuncAttributeMaxDynamicSharedMemorySize, SMEM_DYN);

    k_init<<<512, 256>>>(init);
    k_prep<<<G3, 128>>>(Whh, E, Wih);
    k_prepw<<<G3, 256>>>(Wih);
    k_gx<<<dim3(G3 / 128, (BB * TT) / 128), 256>>>(ctx, bih);
    k_seq<<<GRID, NTHR, SMEM_DYN>>>(bhh, W1, b1, W2, b2, out);
}